// round 14
// baseline (speedup 1.0000x reference)
#include <cuda_runtime.h>
#include <cuda_fp16.h>
#include <cstdint>

#define BATCH 4
#define CH    384
#define HWPIX 4096
#define ROWS  (BATCH*HWPIX)      // 16384
#define WELEMS (CH*CH)           // 147456

// -------- scratch (static device globals; no allocation allowed) --------
__device__ __align__(16) __half g_vifh[ROWS*CH];
__device__ __align__(16) __half g_irfh[ROWS*CH];
__device__ __align__(16) __half g_s1h [ROWS*CH];
__device__ __align__(16) __half g_axh [ROWS*CH];
__device__ __align__(16) __half g_axh2[ROWS*CH];
__device__ __align__(16) float  g_s1n [ROWS*CH];   // s1 in NCHW (for residual epilogue)
__device__ __align__(16) __half g_q1  [ROWS*CH];
__device__ __align__(16) __half g_k1  [ROWS*CH];
__device__ __align__(16) __half g_v1  [ROWS*CH];
__device__ __align__(16) __half g_q2  [ROWS*CH];
__device__ __align__(16) __half g_k2  [ROWS*CH];
__device__ __align__(16) __half g_v2  [ROWS*CH];
__device__ __align__(16) __half g_wh  [8*WELEMS];  // fp16 weights

// ==================== PTX helpers (base sm_103-safe) ====================
__device__ __forceinline__ uint32_t smem_u32(const void* p) {
    uint32_t a;
    asm("{ .reg .u64 t; cvta.to.shared.u64 t, %1; cvt.u32.u64 %0, t; }" : "=r"(a) : "l"(p));
    return a;
}

__device__ __forceinline__ void ldm4(uint32_t* r, uint32_t addr) {
    asm volatile("ldmatrix.sync.aligned.m8n8.x4.shared.b16 {%0,%1,%2,%3}, [%4];"
        : "=r"(r[0]), "=r"(r[1]), "=r"(r[2]), "=r"(r[3]) : "r"(addr));
}

__device__ __forceinline__ void mma16816(float* c, const uint32_t* a, uint32_t b0, uint32_t b1) {
    asm volatile("mma.sync.aligned.m16n8k16.row.col.f32.f16.f16.f32 "
        "{%0,%1,%2,%3}, {%4,%5,%6,%7}, {%8,%9}, {%0,%1,%2,%3};"
        : "+f"(c[0]), "+f"(c[1]), "+f"(c[2]), "+f"(c[3])
        : "r"(a[0]), "r"(a[1]), "r"(a[2]), "r"(a[3]), "r"(b0), "r"(b1));
}

__device__ __forceinline__ void cpasync16(uint32_t saddr, const void* gaddr) {
    asm volatile("cp.async.cg.shared.global [%0], [%1], 16;" :: "r"(saddr), "l"(gaddr));
}
#define CP_COMMIT() asm volatile("cp.async.commit_group;" ::: "memory")
template<int N> __device__ __forceinline__ void cp_wait() {
    asm volatile("cp.async.wait_group %0;" :: "n"(N) : "memory");
}

// ==================== weight fp32 -> fp16 conversion ====================
struct WPtrs { const float* w[8]; };

__global__ __launch_bounds__(256) void convw_kernel(WPtrs wp) {
    int m = blockIdx.y;
    int i = (blockIdx.x * 256 + threadIdx.x) * 4;       // WELEMS/4 = 36864 -> 144 blocks
    float4 v = *reinterpret_cast<const float4*>(wp.w[m] + i);
    __half2 h0 = __floats2half2_rn(v.x, v.y);
    __half2 h1 = __floats2half2_rn(v.z, v.w);
    uint2 pk;
    pk.x = *reinterpret_cast<uint32_t*>(&h0);
    pk.y = *reinterpret_cast<uint32_t*>(&h1);
    *reinterpret_cast<uint2*>(g_wh + (size_t)m * WELEMS + i) = pk;
}

// ==================== fused single-pass LayerNorm ====================
#define LNP 16
#define LNS 17
#define LN_ARR (CH*LNS)            // 6528 floats per array
#define LN_SMEM (2*LN_ARR*4)       // 52224 bytes dynamic

__global__ __launch_bounds__(256) void ln_fused_kernel(
    const float* __restrict__ vi, const float* __restrict__ ir,
    const float* __restrict__ gvi, const float* __restrict__ bvi,
    const float* __restrict__ gir, const float* __restrict__ bir)
{
    extern __shared__ float dsm[];
    float* sva = dsm;               // [384][17]
    float* sve = dsm + LN_ARR;
    __shared__ float sgv[CH], sbv[CH], sgi[CH], sbi[CH];
    __shared__ float red[256][4];
    __shared__ float4 stat[LNP];

    int tid = threadIdx.x;
    int pix0 = blockIdx.x * LNP;
    int b = pix0 >> 12, p0 = pix0 & 4095;

    for (int i = tid; i < CH; i += 256) {
        sgv[i] = gvi[i]; sbv[i] = bvi[i];
        sgi[i] = gir[i]; sbi[i] = bir[i];
    }

    int pl = tid & 15, cb = tid >> 4;
    const float* basev = vi + (((size_t)b * CH) << 12) + p0 + pl;
    const float* basei = ir + (((size_t)b * CH) << 12) + p0 + pl;
#pragma unroll
    for (int it = 0; it < 24; it++) {
        int c = cb + it * 16;
        sva[c * LNS + pl] = basev[(size_t)c << 12];
        sve[c * LNS + pl] = basei[(size_t)c << 12];
    }
    __syncthreads();

    float s1 = 0.f, s2 = 0.f, s3 = 0.f, s4 = 0.f;
#pragma unroll
    for (int j = 0; j < 24; j++) {
        int c = cb * 24 + j;
        float a = sva[c * LNS + pl];
        float e = sve[c * LNS + pl];
        s1 += a; s2 += a * a; s3 += e; s4 += e * e;
    }
    red[tid][0] = s1; red[tid][1] = s2; red[tid][2] = s3; red[tid][3] = s4;
    __syncthreads();
    if (tid < LNP) {
        float a = 0.f, q = 0.f, e = 0.f, r = 0.f;
#pragma unroll
        for (int s = 0; s < 16; s++) {
            a += red[s * 16 + tid][0]; q += red[s * 16 + tid][1];
            e += red[s * 16 + tid][2]; r += red[s * 16 + tid][3];
        }
        float ma = a * (1.f/CH), me = e * (1.f/CH);
        float va = q * (1.f/CH) - ma * ma;
        float ve = r * (1.f/CH) - me * me;
        float4 st;
        st.x = ma; st.y = rsqrtf(va + 1e-6f);
        st.z = me; st.w = rsqrtf(ve + 1e-6f);
        stat[tid] = st;
    }
    __syncthreads();

    int w = tid >> 5, lane = tid & 31;
#pragma unroll
    for (int pp = 0; pp < 2; pp++) {
        int p = w * 2 + pp;
        float4 st = stat[p];
        size_t rb = (size_t)(pix0 + p) * CH;
#pragma unroll
        for (int j = 0; j < 6; j++) {
            int c = j * 64 + lane * 2;
            float a0 = sva[c * LNS + p], a1 = sva[(c + 1) * LNS + p];
            float e0 = sve[c * LNS + p], e1 = sve[(c + 1) * LNS + p];
            float fv0 = (a0 - st.x) * st.y * sgv[c]     + sbv[c];
            float fv1 = (a1 - st.x) * st.y * sgv[c + 1] + sbv[c + 1];
            float fi0 = (e0 - st.z) * st.w * sgi[c]     + sbi[c];
            float fi1 = (e1 - st.z) * st.w * sgi[c + 1] + sbi[c + 1];
            *reinterpret_cast<__half2*>(g_vifh + rb + c) = __floats2half2_rn(fv0, fv1);
            *reinterpret_cast<__half2*>(g_irfh + rb + c) = __floats2half2_rn(fi0, fi1);
            *reinterpret_cast<__half2*>(g_s1h  + rb + c) = __floats2half2_rn(fv0 - fi0, fv1 - fi1);
        }
    }

    float4 stp = stat[pl];
#pragma unroll
    for (int it = 0; it < 24; it++) {
        int c = cb + it * 16;
        float a = sva[c * LNS + pl], e = sve[c * LNS + pl];
        float fv = (a - stp.x) * stp.y * sgv[c] + sbv[c];
        float fi = (e - stp.z) * stp.w * sgi[c] + sbi[c];
        g_s1n[(((size_t)(b * CH + c)) << 12) + p0 + pl] = fv - fi;
    }
}

// ==================== GEMM common ====================
#define KC      64
#define CRS     72                        // chunk row stride (halves)
#define STAGE_A_BYTES (128*CRS*2)         // 18432
#define STAGE_BYTES   (2*STAGE_A_BYTES)   // 36864
#define NSTAGE  3
#define SM_TOTAL (NSTAGE*STAGE_BYTES)     // 110592
#define STG_RS  129                       // MODE1 staging stride (floats)
#define NTILES  (128*3*6)                 // 2304 qkv tiles

struct BatchArgs {
    const __half* X[6];
    const __half* W[6];
    const float*  bias[6];
    void*         Y[6];
    float         alpha[6];
    const float*  S;
    float         ssign[6];
};

// ==================== persistent qkv GEMM (MODE0, z-batched tiles) ====================
// Tile tt = z*384 + y*128 + x  ->  z problem, o0 = y*128, r0 = x*128.
// Each CTA walks tiles t0, t0+G, ...; all (tile x 6) K-chunks form one cp.async stream.
__global__ __launch_bounds__(256, 2) void gemm_qkv_persistent(BatchArgs ba)
{
    extern __shared__ char smem[];
    uint32_t sbA = smem_u32(smem);
    int tid = threadIdx.x, wid = tid >> 5, lane = tid & 31;
    int mw0 = (wid & 3) * 32;            // warp M origin
    int nw0 = (wid >> 2) * 64;           // warp N origin
    int t0 = blockIdx.x, G = gridDim.x;
    int nt = (NTILES - 1 - t0) / G + 1;  // my tile count
    int nc = nt * 6;

    int lrow = tid >> 3;
    int lch  = tid & 7;

    auto load_chunk_g = [&](int gc, int s) {
        int i = gc / 6, c = gc - i * 6;
        int tt = t0 + i * G;
        int z = tt / 384, rem = tt - z * 384;
        int o0 = (rem >> 7) << 7, r0 = (rem & 127) << 7;
        const __half* gA = ba.X[z] + (size_t)r0 * CH;
        const __half* gB = ba.W[z] + (size_t)o0 * CH;
        uint32_t sbase = sbA + s * STAGE_BYTES;
        int kof = c * KC + lch * 8;
#pragma unroll
        for (int it = 0; it < 4; it++) {
            int row = lrow + it * 32;
            cpasync16(sbase + (uint32_t)((row * CRS + lch * 8) * 2),
                      gA + (size_t)row * CH + kof);
        }
#pragma unroll
        for (int it = 0; it < 4; it++) {
            int row = lrow + it * 32;
            cpasync16(sbase + STAGE_A_BYTES + (uint32_t)((row * CRS + lch * 8) * 2),
                      gB + (size_t)row * CH + kof);
        }
    };

    uint32_t aOff = (uint32_t)(((mw0 + (lane & 15)) * CRS + (lane >> 4) * 8) * 2);
    uint32_t bOff = (uint32_t)(STAGE_A_BYTES +
                    ((nw0 + ((lane >> 4) * 8 + (lane & 7))) * CRS + ((lane >> 3) & 1) * 8) * 2);

    float c[2][8][4];
#pragma unroll
    for (int i = 0; i < 2; i++)
#pragma unroll
        for (int j = 0; j < 8; j++)
#pragma unroll
            for (int q = 0; q < 4; q++) c[i][j][q] = 0.f;

    auto compute = [&](int s) {
        uint32_t aB = sbA + s * STAGE_BYTES + aOff;
        uint32_t bB = sbA + s * STAGE_BYTES + bOff;
#pragma unroll
        for (int ks = 0; ks < 4; ks++) {
            uint32_t a[2][4], b[4][4];
            ldm4(a[0], aB + ks * 32);
            ldm4(a[1], aB + ks * 32 + 16 * CRS * 2);
#pragma unroll
            for (int g = 0; g < 4; g++)
                ldm4(b[g], bB + ks * 32 + g * 16 * CRS * 2);
#pragma unroll
            for (int i = 0; i < 2; i++)
#pragma unroll
                for (int j = 0; j < 8; j++) {
                    const uint32_t* bg = b[j >> 1];
                    uint32_t b0 = (j & 1) ? bg[2] : bg[0];
                    uint32_t b1 = (j & 1) ? bg[3] : bg[1];
                    mma16816(c[i][j], a[i], b0, b1);
                }
        }
    };

    int tq = lane >> 2, tr = lane & 3;

    load_chunk_g(0, 0); CP_COMMIT();
    load_chunk_g(1, 1); CP_COMMIT();

    int c6 = 0, ti = 0, stage = 0;
    for (int gc = 0; gc < nc; gc++) {
        if (gc < nc - 1) cp_wait<1>(); else cp_wait<0>();
        __syncthreads();
        if (gc + 2 < nc) {
            int s2 = stage + 2; if (s2 >= NSTAGE) s2 -= NSTAGE;
            load_chunk_g(gc + 2, s2); CP_COMMIT();
        }
        compute(stage);
        if (++stage == NSTAGE) stage = 0;

        if (c6 == 5) {
            // ---- tile epilogue (registers -> global; overlaps in-flight loads) ----
            int tt = t0 + ti * G;
            int z = tt / 384, rem = tt - z * 384;
            int o0 = (rem >> 7) << 7, r0 = (rem & 127) << 7;
            __half* Y = reinterpret_cast<__half*>(ba.Y[z]);
            const float* bias = ba.bias[z];
            float alpha = ba.alpha[z];
#pragma unroll
            for (int i = 0; i < 2; i++)
#pragma unroll
                for (int j = 0; j < 8; j++) {
                    int colb = nw0 + j * 8 + tr * 2;
                    float b0 = __ldg(bias + o0 + colb);
                    float b1 = __ldg(bias + o0 + colb + 1);
#pragma unroll
                    for (int h = 0; h < 2; h++) {
                        int row = r0 + mw0 + i * 16 + tq + h * 8;
                        __half2 hv = __floats2half2_rn(
                            alpha * c[i][j][h * 2 + 0] + b0,
                            alpha * c[i][j][h * 2 + 1] + b1);
                        *reinterpret_cast<__half2*>(Y + (size_t)row * CH + o0 + colb) = hv;
                    }
                }
#pragma unroll
            for (int i = 0; i < 2; i++)
#pragma unroll
                for (int j = 0; j < 8; j++)
#pragma unroll
                    for (int q = 0; q < 4; q++) c[i][j][q] = 0.f;
            ti++; c6 = 0;
        } else c6++;
    }
}

// ==================== projection GEMM (MODE1: NCHW scatter + residual) ====================
__global__ __launch_bounds__(256, 2) void gemm_proj_kernel(BatchArgs ba)
{
    extern __shared__ char smem[];
    __shared__ float sbias[128];
    uint32_t sbA = smem_u32(smem);
    int z = blockIdx.z;
    const __half* __restrict__ X = ba.X[z];
    const __half* __restrict__ W = ba.W[z];

    int tid = threadIdx.x, wid = tid >> 5, lane = tid & 31;
    int r0 = blockIdx.x * 128, o0 = blockIdx.y * 128;
    int mw0 = (wid & 3) * 32;
    int nw0 = (wid >> 2) * 64;

    if (tid < 128) sbias[tid] = ba.bias[z][o0 + tid];

    int lrow = tid >> 3;
    int lch  = tid & 7;
    const __half* gA = X + (size_t)r0 * CH;
    const __half* gB = W + (size_t)o0 * CH;

    auto load_chunk = [&](int c, int s) {
        uint32_t sbase = sbA + s * STAGE_BYTES;
        int kof = c * KC + lch * 8;
#pragma unroll
        for (int it = 0; it < 4; it++) {
            int row = lrow + it * 32;
            cpasync16(sbase + (uint32_t)((row * CRS + lch * 8) * 2),
                      gA + (size_t)row * CH + kof);
        }
#pragma unroll
        for (int it = 0; it < 4; it++) {
            int row = lrow + it * 32;
            cpasync16(sbase + STAGE_A_BYTES + (uint32_t)((row * CRS + lch * 8) * 2),
                      gB + (size_t)row * CH + kof);
        }
    };

    uint32_t aOff = (uint32_t)(((mw0 + (lane & 15)) * CRS + (lane >> 4) * 8) * 2);
    uint32_t bOff = (uint32_t)(STAGE_A_BYTES +
                    ((nw0 + ((lane >> 4) * 8 + (lane & 7))) * CRS + ((lane >> 3) & 1) * 8) * 2);

    float c[2][8][4];
#pragma unroll
    for (int i = 0; i < 2; i++)
#pragma unroll
        for (int j = 0; j < 8; j++)
#pragma unroll
            for (int q = 0; q < 4; q++) c[i][j][q] = 0.f;

    auto compute = [&](int s) {
        uint32_t aB = sbA + s * STAGE_BYTES + aOff;
        uint32_t bB = sbA + s * STAGE_BYTES + bOff;
#pragma unroll
        for (int ks = 0; ks < 4; ks++) {
            uint32_t a[2][4], b[4][4];
            ldm4(a[0], aB + ks * 32);
            ldm4(a[1], aB + ks * 32 + 16 * CRS * 2);
#pragma unroll
            for (int g = 0; g < 4; g++)
                ldm4(b[g], bB + ks * 32 + g * 16 * CRS * 2);
#pragma unroll
            for (int i = 0; i < 2; i++)
#pragma unroll
                for (int j = 0; j < 8; j++) {
                    const uint32_t* bg = b[j >> 1];
                    uint32_t b0 = (j & 1) ? bg[2] : bg[0];
                    uint32_t b1 = (j & 1) ? bg[3] : bg[1];
                    mma16816(c[i][j], a[i], b0, b1);
                }
        }
    };

    load_chunk(0, 0); CP_COMMIT();
    load_chunk(1, 1); CP_COMMIT();
#pragma unroll
    for (int cc = 0; cc < 6; cc++) {
        if (cc < 5) cp_wait<1>(); else cp_wait<0>();
        __syncthreads();
        if (cc < 4) { load_chunk(cc + 2, (cc + 2) % NSTAGE); CP_COMMIT(); }
        compute(cc % NSTAGE);
    }

    int tq = lane >> 2, tr = lane & 3;

    float* Y = reinterpret_cast<float*>(ba.Y[z]);
    const float* S = ba.S;
    float ssign = ba.ssign[z];
    float* smemf = reinterpret_cast<float*>(smem);
    __syncthreads();
#pragma unroll
    for (int i = 0; i < 2; i++)
#pragma unroll
        for (int j = 0; j < 8; j++) {
            int colb = nw0 + j * 8 + tr * 2;
#pragma unroll
            for (int h = 0; h < 2; h++) {
                int row = mw0 + i * 16 + tq + h * 8;
                smemf[row * STG_RS + colb]     = c[i][j][h * 2 + 0];
                smemf[row * STG_RS + colb + 1] = c[i][j][h * 2 + 1];
            }
        }
    __syncthreads();
    int b = r0 >> 12, p0r = r0 & 4095;
    for (int tk = wid * 64; tk < wid * 64 + 64; tk++) {
        int col = tk >> 2, rb = tk & 3;
        int row = rb * 32 + lane;
        float val = smemf[row * STG_RS + col];
        size_t addr = (((size_t)(b * CH + o0 + col)) << 12) + p0r + row;
        Y[addr] = val + sbias[col] + ssign * S[addr];
    }
}

// ==================== dilated 3x3 window attention ====================
// 4 units/warp, 8 lanes/unit; lane owns 8 contiguous head-dims.
struct AttnArgs {
    const __half* q[2]; const __half* k[2]; const __half* v[2]; __half* o[2];
};

__global__ __launch_bounds__(256) void attn_kernel(AttnArgs aa)
{
    int tid  = threadIdx.x;
    int wid  = tid >> 5, lane = tid & 31;
    int g    = lane & 7;                       // lane within unit group
    int u    = blockIdx.x * 32 + wid * 4 + (lane >> 3);   // 0..196607
    int sel  = u >= 98304;
    int unit = u - sel * 98304;

    int pix  = unit & 4095;
    int t    = unit >> 12;
    int head = t & 1;  t >>= 1;
    int di   = t % 3;
    int b    = t / 3;
    int dil  = di + 1;
    int y0   = pix >> 6, x0 = pix & 63;
    int chan = di * 128 + head * 64;

    size_t sbase = (size_t)b * HWPIX * CH + chan + g * 8;  // lane's 8-dim slice
    const char* kb = reinterpret_cast<const char*>(aa.k[sel] + sbase);
    const char* vb = reinterpret_cast<const char*>(aa.v[sel] + sbase);

    uint4 qr = *reinterpret_cast<const uint4*>(aa.q[sel] + sbase + (size_t)pix * CH);
    __half2 q2[4];
    q2[0] = *reinterpret_cast<__half2*>(&qr.x);
    q2[1] = *reinterpret_cast<__half2*>(&qr.y);
    q2[2] = *reinterpret_cast<__half2*>(&qr.z);
    q2[3] = *reinterpret_cast<__half2*>(&qr.w);

    // ---- pass 1: logits + cached offsets ----
    uint32_t offs[9];
    float logit[9];
    unsigned okm = 0;
#pragma unroll
    for (int n = 0; n < 9; n++) {
        int iy = n / 3 - 1, ix = n % 3 - 1;
        int yn = y0 + iy * dil, xn = x0 + ix * dil;
        bool ok = ((unsigned)yn < 64u) && ((unsigned)xn < 64u);
        int npix = ok ? (yn * 64 + xn) : pix;       // safe address for OOB
        offs[n] = (uint32_t)npix * (CH * 2);
        okm |= (unsigned)ok << n;
        uint4 kr = *reinterpret_cast<const uint4*>(kb + offs[n]);
        __half2 acc = __hmul2(q2[0], *reinterpret_cast<__half2*>(&kr.x));
        acc = __hfma2(q2[1], *reinterpret_cast<__half2*>(&kr.y), acc);
        acc = __hfma2(q2[2], *reinterpret_cast<__half2*>(&kr.z), acc);
        acc = __hfma2(q2[3], *reinterpret_cast<__half2*>(&kr.w), acc);
        float2 f = __half22float2(acc);
        float d = f.x + f.y;
        d += __shfl_xor_sync(0xffffffffu, d, 1);
        d += __shfl_xor_sync(0xffffffffu, d, 2);
        d += __shfl_xor_sync(0xffffffffu, d, 4);
        logit[n] = ok ? d * 0.125f : 0.f;   // SCALE = 64^-0.5; OOB taps -> logit 0 (zero-padded k)
    }

    // ---- softmax ----
    float m = logit[0];
#pragma unroll
    for (int n = 1; n < 9; n++) m = fmaxf(m, logit[n]);
    float den = 0.f;
    __half2 pw[9];
#pragma unroll
    for (int n = 0; n < 9; n++) {
        float p = __expf(logit[n] - m);
        den += p;                            // zero-padded taps contribute exp(0-m)
        pw[n] = __float2half2_rn(((okm >> n) & 1u) ? p : 0.f);   // weight 0 for OOB V
    }
    float inv = 1.f / den;

    // ---- pass 2: branchless fp16 V accumulation ----
    __half2 ac[4];
    ac[0] = __floats2half2_rn(0.f, 0.f);
    ac[1] = ac[0]; ac[2] = ac[0]; ac[3] = ac[0];
#pragma unroll
    for (int n = 0; n < 9; n++) {
        uint4 vr = *reinterpret_cast<const uint4*>(vb + offs[n]);
        ac[0] = __hfma2(pw[n], *reinterpret_cast<__half2*>(&vr.x), ac[0]);
        ac[1] = __hfma2(pw[n], *reinterpret_cast<__half2*>(&vr.y), ac[1]);
        ac[2] = __hfma2(pw[n], *reinterpret_cast<__half2*>(&vr.z), ac[2]);
        ac[3] = __hfma2(pw[n], *reinterpret_cast<__half2*>(&vr.w), ac[3]);
    }

    // ---- normalize (fp32) + store 8 halves ----
    int G  = pix * 2 + head;
    int F2 = (G >> 6) * 12288 + (G & 63) * 192 + di * 64;
    uint4 ov;
    uint32_t* ovp = reinterpret_cast<uint32_t*>(&ov);
#pragma unroll
    for (int i = 0; i < 4; i++) {
        float2 f = __half22float2(ac[i]);
        __half2 h = __floats2half2_rn(f.x * inv, f.y * inv);
        ovp[i] = *reinterpret_cast<uint32_t*>(&h);
    }
    *reinterpret_cast<uint4*>(aa.o[sel] + (size_t)b * HWPIX * CH + F2 + g * 8) = ov;
}

// ==================== launch ====================
extern "C" void kernel_launch(void* const* d_in, const int* in_sizes, int n_in,
                              void* d_out, int out_size)
{
    const float* vi  = (const float*)d_in[0];
    const float* ir  = (const float*)d_in[1];
    const float* gvi = (const float*)d_in[2];
    const float* bvi = (const float*)d_in[3];
    const float* gir = (const float*)d_in[4];
    const float* bir = (const float*)d_in[5];
    const float* wq1 = (const float*)d_in[6];
    const float* bq1 = (const float*)d_in[7];
    const float* wk1 = (const float*)d_in[8];
    const float* bk1 = (const float*)d_in[9];
    const float* wv1 = (const float*)d_in[10];
    const float* bv1 = (const float*)d_in[11];
    const float* wp1 = (const float*)d_in[12];
    const float* bp1 = (const float*)d_in[13];
    const float* wq2 = (const float*)d_in[14];
    const float* bq2 = (const float*)d_in[15];
    const float* wk2 = (const float*)d_in[16];
    const float* bk2 = (const float*)d_in[17];
    const float* wv2 = (const float*)d_in[18];
    const float* bv2 = (const float*)d_in[19];
    const float* wp2 = (const float*)d_in[20];
    const float* bp2 = (const float*)d_in[21];
    float* out = (float*)d_out;

    __half *p_vifh, *p_irfh, *p_s1h, *p_axh, *p_axh2, *p_wh;
    __half *p_q1, *p_k1, *p_v1, *p_q2, *p_k2, *p_v2;
    float  *p_s1n;
    cudaGetSymbolAddress((void**)&p_vifh, g_vifh);
    cudaGetSymbolAddress((void**)&p_irfh, g_irfh);
    cudaGetSymbolAddress((void**)&p_s1h,  g_s1h);
    cudaGetSymbolAddress((void**)&p_axh,  g_axh);
    cudaGetSymbolAddress((void**)&p_axh2, g_axh2);
    cudaGetSymbolAddress((void**)&p_wh,   g_wh);
    cudaGetSymbolAddress((void**)&p_s1n,  g_s1n);
    cudaGetSymbolAddress((void**)&p_q1,   g_q1);
    cudaGetSymbolAddress((void**)&p_k1,   g_k1);
    cudaGetSymbolAddress((void**)&p_v1,   g_v1);
    cudaGetSymbolAddress((void**)&p_q2,   g_q2);
    cudaGetSymbolAddress((void**)&p_k2,   g_k2);
    cudaGetSymbolAddress((void**)&p_v2,   g_v2);

    int nsm = 148;
    cudaDeviceGetAttribute(&nsm, cudaDevAttrMultiProcessorCount, 0);

    cudaFuncSetAttribute(gemm_qkv_persistent, cudaFuncAttributeMaxDynamicSharedMemorySize, SM_TOTAL);
    cudaFuncSetAttribute(gemm_proj_kernel,    cudaFuncAttributeMaxDynamicSharedMemorySize, SM_TOTAL);
    cudaFuncSetAttribute(ln_fused_kernel,     cudaFuncAttributeMaxDynamicSharedMemorySize, LN_SMEM);

    // weights -> fp16 (order: wq1,wk1,wv1,wp1,wq2,wk2,wv2,wp2)
    WPtrs wp;
    wp.w[0] = wq1; wp.w[1] = wk1; wp.w[2] = wv1; wp.w[3] = wp1;
    wp.w[4] = wq2; wp.w[5] = wk2; wp.w[6] = wv2; wp.w[7] = wp2;
    convw_kernel<<<dim3(144, 8), 256>>>(wp);

    ln_fused_kernel<<<ROWS / LNP, 256, LN_SMEM>>>(vi, ir, gvi, bvi, gir, bir);

    // ---- all six pre-attention GEMMs: persistent CTAs, one cp.async stream ----
    BatchArgs qkv = {};
    qkv.X[0] = p_s1h;  qkv.W[0] = p_wh + 0*WELEMS; qkv.bias[0] = bq1; qkv.Y[0] = p_q1; qkv.alpha[0] =  1.f;
    qkv.X[1] = p_s1h;  qkv.W[1] = p_wh + 4*WELEMS; qkv.bias[1] = bq2; qkv.Y[1] = p_q2; qkv.alpha[1] = -1.f;
    qkv.X[2] = p_vifh; qkv.W[2] = p_wh + 1*WELEMS; qkv.bias[2] = bk1; qkv.Y[2] = p_k1; qkv.alpha[2] =  1.f;
    qkv.X[3] = p_vifh; qkv.W[3] = p_wh + 2*WELEMS; qkv.bias[3] = bv1; qkv.Y[3] = p_v1; qkv.alpha[3] =  1.f;
    qkv.X[4] = p_irfh; qkv.W[4] = p_wh + 5*WELEMS; qkv.bias[4] = bk2; qkv.Y[4] = p_k2; qkv.alpha[4] =  1.f;
    qkv.X[5] = p_irfh; qkv.W[5] = p_wh + 6*WELEMS; qkv.bias[5] = bv2; qkv.Y[5] = p_v2; qkv.alpha[5] =  1.f;
    gemm_qkv_persistent<<<2 * nsm, 256, SM_TOTAL>>>(qkv);

    // ---- both attentions in one launch (4 units/warp) ----
    AttnArgs aa;
    aa.q[0] = p_q1; aa.k[0] = p_k1; aa.v[0] = p_v1; aa.o[0] = p_axh;
    aa.q[1] = p_q2; aa.k[1] = p_k2; aa.v[1] = p_v2; aa.o[1] = p_axh2;
    attn_kernel<<<6144, 256>>>(aa);

    // ---- both projections (+ residual, NCHW scatter) in one launch ----
    BatchArgs pj = {};
    pj.X[0] = p_axh;  pj.W[0] = p_wh + 3*WELEMS; pj.bias[0] = bp1; pj.Y[0] = out;                      pj.alpha[0] = 1.f; pj.ssign[0] =  1.f;
    pj.X[1] = p_axh2; pj.W[1] = p_wh + 7*WELEMS; pj.bias[1] = bp2; pj.Y[1] = out + (size_t)ROWS * CH;  pj.alpha[1] = 1.f; pj.ssign[1] = -1.f;
    pj.S = p_s1n;
    gemm_proj_kernel<<<dim3(ROWS/128, CH/128, 2), 256, SM_TOTAL>>>(pj);
}

// round 15
// speedup vs baseline: 1.0363x; 1.0363x over previous
#include <cuda_runtime.h>
#include <cuda_fp16.h>
#include <cstdint>

#define BATCH 4
#define CH    384
#define HWPIX 4096
#define ROWS  (BATCH*HWPIX)      // 16384
#define WELEMS (CH*CH)           // 147456

// -------- scratch (static device globals; no allocation allowed) --------
__device__ __align__(16) __half g_vifh[ROWS*CH];
__device__ __align__(16) __half g_irfh[ROWS*CH];
__device__ __align__(16) __half g_s1h [ROWS*CH];
__device__ __align__(16) __half g_axh [ROWS*CH];
__device__ __align__(16) __half g_axh2[ROWS*CH];
__device__ __align__(16) float  g_s1n [ROWS*CH];   // s1 in NCHW (for residual epilogue)
__device__ __align__(16) __half g_q1  [ROWS*CH];
__device__ __align__(16) __half g_k1  [ROWS*CH];
__device__ __align__(16) __half g_v1  [ROWS*CH];
__device__ __align__(16) __half g_q2  [ROWS*CH];
__device__ __align__(16) __half g_k2  [ROWS*CH];
__device__ __align__(16) __half g_v2  [ROWS*CH];
__device__ __align__(16) __half g_wh  [8*WELEMS];  // fp16 weights

// ==================== PTX helpers (base sm_103-safe) ====================
__device__ __forceinline__ uint32_t smem_u32(const void* p) {
    uint32_t a;
    asm("{ .reg .u64 t; cvta.to.shared.u64 t, %1; cvt.u32.u64 %0, t; }" : "=r"(a) : "l"(p));
    return a;
}

__device__ __forceinline__ void ldm4(uint32_t* r, uint32_t addr) {
    asm volatile("ldmatrix.sync.aligned.m8n8.x4.shared.b16 {%0,%1,%2,%3}, [%4];"
        : "=r"(r[0]), "=r"(r[1]), "=r"(r[2]), "=r"(r[3]) : "r"(addr));
}

__device__ __forceinline__ void mma16816(float* c, const uint32_t* a, uint32_t b0, uint32_t b1) {
    asm volatile("mma.sync.aligned.m16n8k16.row.col.f32.f16.f16.f32 "
        "{%0,%1,%2,%3}, {%4,%5,%6,%7}, {%8,%9}, {%0,%1,%2,%3};"
        : "+f"(c[0]), "+f"(c[1]), "+f"(c[2]), "+f"(c[3])
        : "r"(a[0]), "r"(a[1]), "r"(a[2]), "r"(a[3]), "r"(b0), "r"(b1));
}

__device__ __forceinline__ void cpasync16(uint32_t saddr, const void* gaddr) {
    asm volatile("cp.async.cg.shared.global [%0], [%1], 16;" :: "r"(saddr), "l"(gaddr));
}
#define CP_COMMIT() asm volatile("cp.async.commit_group;" ::: "memory")
template<int N> __device__ __forceinline__ void cp_wait() {
    asm volatile("cp.async.wait_group %0;" :: "n"(N) : "memory");
}

// ==================== weight fp32 -> fp16 conversion ====================
struct WPtrs { const float* w[8]; };

__global__ __launch_bounds__(256) void convw_kernel(WPtrs wp) {
    int m = blockIdx.y;
    int i = (blockIdx.x * 256 + threadIdx.x) * 4;       // WELEMS/4 = 36864 -> 144 blocks
    float4 v = *reinterpret_cast<const float4*>(wp.w[m] + i);
    __half2 h0 = __floats2half2_rn(v.x, v.y);
    __half2 h1 = __floats2half2_rn(v.z, v.w);
    uint2 pk;
    pk.x = *reinterpret_cast<uint32_t*>(&h0);
    pk.y = *reinterpret_cast<uint32_t*>(&h1);
    *reinterpret_cast<uint2*>(g_wh + (size_t)m * WELEMS + i) = pk;
}

// ==================== fused single-pass LayerNorm ====================
#define LNP 16
#define LNS 17
#define LN_ARR (CH*LNS)            // 6528 floats per array
#define LN_SMEM (2*LN_ARR*4)       // 52224 bytes dynamic

__global__ __launch_bounds__(256) void ln_fused_kernel(
    const float* __restrict__ vi, const float* __restrict__ ir,
    const float* __restrict__ gvi, const float* __restrict__ bvi,
    const float* __restrict__ gir, const float* __restrict__ bir)
{
    extern __shared__ float dsm[];
    float* sva = dsm;               // [384][17]
    float* sve = dsm + LN_ARR;
    __shared__ float sgv[CH], sbv[CH], sgi[CH], sbi[CH];
    __shared__ float red[256][4];
    __shared__ float4 stat[LNP];

    int tid = threadIdx.x;
    int pix0 = blockIdx.x * LNP;
    int b = pix0 >> 12, p0 = pix0 & 4095;

    for (int i = tid; i < CH; i += 256) {
        sgv[i] = gvi[i]; sbv[i] = bvi[i];
        sgi[i] = gir[i]; sbi[i] = bir[i];
    }

    int pl = tid & 15, cb = tid >> 4;
    const float* basev = vi + (((size_t)b * CH) << 12) + p0 + pl;
    const float* basei = ir + (((size_t)b * CH) << 12) + p0 + pl;
#pragma unroll
    for (int it = 0; it < 24; it++) {
        int c = cb + it * 16;
        sva[c * LNS + pl] = basev[(size_t)c << 12];
        sve[c * LNS + pl] = basei[(size_t)c << 12];
    }
    __syncthreads();

    float s1 = 0.f, s2 = 0.f, s3 = 0.f, s4 = 0.f;
#pragma unroll
    for (int j = 0; j < 24; j++) {
        int c = cb * 24 + j;
        float a = sva[c * LNS + pl];
        float e = sve[c * LNS + pl];
        s1 += a; s2 += a * a; s3 += e; s4 += e * e;
    }
    red[tid][0] = s1; red[tid][1] = s2; red[tid][2] = s3; red[tid][3] = s4;
    __syncthreads();
    if (tid < LNP) {
        float a = 0.f, q = 0.f, e = 0.f, r = 0.f;
#pragma unroll
        for (int s = 0; s < 16; s++) {
            a += red[s * 16 + tid][0]; q += red[s * 16 + tid][1];
            e += red[s * 16 + tid][2]; r += red[s * 16 + tid][3];
        }
        float ma = a * (1.f/CH), me = e * (1.f/CH);
        float va = q * (1.f/CH) - ma * ma;
        float ve = r * (1.f/CH) - me * me;
        float4 st;
        st.x = ma; st.y = rsqrtf(va + 1e-6f);
        st.z = me; st.w = rsqrtf(ve + 1e-6f);
        stat[tid] = st;
    }
    __syncthreads();

    int w = tid >> 5, lane = tid & 31;
#pragma unroll
    for (int pp = 0; pp < 2; pp++) {
        int p = w * 2 + pp;
        float4 st = stat[p];
        size_t rb = (size_t)(pix0 + p) * CH;
#pragma unroll
        for (int j = 0; j < 6; j++) {
            int c = j * 64 + lane * 2;
            float a0 = sva[c * LNS + p], a1 = sva[(c + 1) * LNS + p];
            float e0 = sve[c * LNS + p], e1 = sve[(c + 1) * LNS + p];
            float fv0 = (a0 - st.x) * st.y * sgv[c]     + sbv[c];
            float fv1 = (a1 - st.x) * st.y * sgv[c + 1] + sbv[c + 1];
            float fi0 = (e0 - st.z) * st.w * sgi[c]     + sbi[c];
            float fi1 = (e1 - st.z) * st.w * sgi[c + 1] + sbi[c + 1];
            *reinterpret_cast<__half2*>(g_vifh + rb + c) = __floats2half2_rn(fv0, fv1);
            *reinterpret_cast<__half2*>(g_irfh + rb + c) = __floats2half2_rn(fi0, fi1);
            *reinterpret_cast<__half2*>(g_s1h  + rb + c) = __floats2half2_rn(fv0 - fi0, fv1 - fi1);
        }
    }

    float4 stp = stat[pl];
#pragma unroll
    for (int it = 0; it < 24; it++) {
        int c = cb + it * 16;
        float a = sva[c * LNS + pl], e = sve[c * LNS + pl];
        float fv = (a - stp.x) * stp.y * sgv[c] + sbv[c];
        float fi = (e - stp.z) * stp.w * sgi[c] + sbi[c];
        g_s1n[(((size_t)(b * CH + c)) << 12) + p0 + pl] = fv - fi;
    }
}

// ==================== pipelined HMMA GEMM (z-batched) — R11/R13 proven config ====================
#define KC      64
#define CRS     72                        // chunk row stride (halves)
#define STAGE_A_BYTES (128*CRS*2)         // 18432
#define STAGE_BYTES   (2*STAGE_A_BYTES)   // 36864
#define NSTAGE  3
#define SM_TOTAL (NSTAGE*STAGE_BYTES)     // 110592
#define STG_RS  129                       // MODE1 staging stride (floats)

struct BatchArgs {
    const __half* X[6];
    const __half* W[6];
    const float*  bias[6];
    void*         Y[6];
    float         alpha[6];
    const float*  S;
    float         ssign[6];
};

template<int MODE>
__global__ __launch_bounds__(256, 2) void gemm_tc_kernel(BatchArgs ba)
{
    extern __shared__ char smem[];
    __shared__ float sbias[128];
    uint32_t sbA = smem_u32(smem);
    int z = blockIdx.z;
    const __half* __restrict__ X = ba.X[z];
    const __half* __restrict__ W = ba.W[z];
    float alpha = ba.alpha[z];

    int tid = threadIdx.x, wid = tid >> 5, lane = tid & 31;
    int r0 = blockIdx.x * 128, o0 = blockIdx.y * 128;
    int mw0 = (wid & 3) * 32;            // warp M origin
    int nw0 = (wid >> 2) * 64;           // warp N origin

    if (tid < 128) sbias[tid] = ba.bias[z][o0 + tid];

    int lrow = tid >> 3;
    int lch  = tid & 7;
    const __half* gA = X + (size_t)r0 * CH;
    const __half* gB = W + (size_t)o0 * CH;

    auto load_chunk = [&](int c, int s) {
        uint32_t sbase = sbA + s * STAGE_BYTES;
        int kof = c * KC + lch * 8;
#pragma unroll
        for (int it = 0; it < 4; it++) {
            int row = lrow + it * 32;
            cpasync16(sbase + (uint32_t)((row * CRS + lch * 8) * 2),
                      gA + (size_t)row * CH + kof);
        }
#pragma unroll
        for (int it = 0; it < 4; it++) {
            int row = lrow + it * 32;
            cpasync16(sbase + STAGE_A_BYTES + (uint32_t)((row * CRS + lch * 8) * 2),
                      gB + (size_t)row * CH + kof);
        }
    };

    uint32_t aOff = (uint32_t)(((mw0 + (lane & 15)) * CRS + (lane >> 4) * 8) * 2);
    uint32_t bOff = (uint32_t)(STAGE_A_BYTES +
                    ((nw0 + ((lane >> 4) * 8 + (lane & 7))) * CRS + ((lane >> 3) & 1) * 8) * 2);

    float c[2][8][4];
#pragma unroll
    for (int i = 0; i < 2; i++)
#pragma unroll
        for (int j = 0; j < 8; j++)
#pragma unroll
            for (int q = 0; q < 4; q++) c[i][j][q] = 0.f;

    auto compute = [&](int s) {
        uint32_t aB = sbA + s * STAGE_BYTES + aOff;
        uint32_t bB = sbA + s * STAGE_BYTES + bOff;
#pragma unroll
        for (int ks = 0; ks < 4; ks++) {
            uint32_t a[2][4], b[4][4];
            ldm4(a[0], aB + ks * 32);
            ldm4(a[1], aB + ks * 32 + 16 * CRS * 2);
#pragma unroll
            for (int g = 0; g < 4; g++)
                ldm4(b[g], bB + ks * 32 + g * 16 * CRS * 2);
#pragma unroll
            for (int i = 0; i < 2; i++)
#pragma unroll
                for (int j = 0; j < 8; j++) {
                    const uint32_t* bg = b[j >> 1];
                    uint32_t b0 = (j & 1) ? bg[2] : bg[0];
                    uint32_t b1 = (j & 1) ? bg[3] : bg[1];
                    mma16816(c[i][j], a[i], b0, b1);
                }
        }
    };

    load_chunk(0, 0); CP_COMMIT();
    load_chunk(1, 1); CP_COMMIT();
#pragma unroll
    for (int cc = 0; cc < 6; cc++) {
        if (cc < 5) cp_wait<1>(); else cp_wait<0>();
        __syncthreads();
        if (cc < 4) { load_chunk(cc + 2, (cc + 2) % NSTAGE); CP_COMMIT(); }
        compute(cc % NSTAGE);
    }

    int tq = lane >> 2, tr = lane & 3;

    if (MODE == 0) {
        __half* Y = reinterpret_cast<__half*>(ba.Y[z]);
#pragma unroll
        for (int i = 0; i < 2; i++)
#pragma unroll
            for (int j = 0; j < 8; j++) {
                int colb = nw0 + j * 8 + tr * 2;
#pragma unroll
                for (int h = 0; h < 2; h++) {
                    int row = r0 + mw0 + i * 16 + tq + h * 8;
                    __half2 hv = __floats2half2_rn(
                        alpha * c[i][j][h * 2 + 0] + sbias[colb],
                        alpha * c[i][j][h * 2 + 1] + sbias[colb + 1]);
                    *reinterpret_cast<__half2*>(Y + (size_t)row * CH + o0 + colb) = hv;
                }
            }
    } else {
        float* Y = reinterpret_cast<float*>(ba.Y[z]);
        const float* S = ba.S;
        float ssign = ba.ssign[z];
        float* smemf = reinterpret_cast<float*>(smem);
        __syncthreads();
#pragma unroll
        for (int i = 0; i < 2; i++)
#pragma unroll
            for (int j = 0; j < 8; j++) {
                int colb = nw0 + j * 8 + tr * 2;
#pragma unroll
                for (int h = 0; h < 2; h++) {
                    int row = mw0 + i * 16 + tq + h * 8;
                    smemf[row * STG_RS + colb]     = c[i][j][h * 2 + 0];
                    smemf[row * STG_RS + colb + 1] = c[i][j][h * 2 + 1];
                }
            }
        __syncthreads();
        int b = r0 >> 12, p0r = r0 & 4095;
        for (int tk = wid * 64; tk < wid * 64 + 64; tk++) {
            int col = tk >> 2, rb = tk & 3;
            int row = rb * 32 + lane;
            float val = smemf[row * STG_RS + col];
            size_t addr = (((size_t)(b * CH + o0 + col)) << 12) + p0r + row;
            Y[addr] = val + sbias[col] + ssign * S[addr];
        }
    }
}

// ==================== dilated 3x3 window attention ====================
// 4 units/warp, 8 lanes/unit; lane owns 8 contiguous head-dims.
// Offsets cached from pass 1 (OOB -> safe own-pixel addr, weight 0);
// pass 2 branchless fp16 hfma2 with NORMALIZED weights (inv folded into pw).
struct AttnArgs {
    const __half* q[2]; const __half* k[2]; const __half* v[2]; __half* o[2];
};

__global__ __launch_bounds__(256) void attn_kernel(AttnArgs aa)
{
    int tid  = threadIdx.x;
    int wid  = tid >> 5, lane = tid & 31;
    int g    = lane & 7;                       // lane within unit group
    int u    = blockIdx.x * 32 + wid * 4 + (lane >> 3);   // 0..196607
    int sel  = u >= 98304;
    int unit = u - sel * 98304;

    int pix  = unit & 4095;
    int t    = unit >> 12;
    int head = t & 1;  t >>= 1;
    int di   = t % 3;
    int b    = t / 3;
    int dil  = di + 1;
    int y0   = pix >> 6, x0 = pix & 63;
    int chan = di * 128 + head * 64;

    size_t sbase = (size_t)b * HWPIX * CH + chan + g * 8;  // lane's 8-dim slice
    const char* kb = reinterpret_cast<const char*>(aa.k[sel] + sbase);
    const char* vb = reinterpret_cast<const char*>(aa.v[sel] + sbase);

    uint4 qr = *reinterpret_cast<const uint4*>(aa.q[sel] + sbase + (size_t)pix * CH);
    __half2 q2[4];
    q2[0] = *reinterpret_cast<__half2*>(&qr.x);
    q2[1] = *reinterpret_cast<__half2*>(&qr.y);
    q2[2] = *reinterpret_cast<__half2*>(&qr.z);
    q2[3] = *reinterpret_cast<__half2*>(&qr.w);

    // ---- pass 1: logits + cached offsets ----
    uint32_t offs[9];
    float logit[9];
    unsigned okm = 0;
#pragma unroll
    for (int n = 0; n < 9; n++) {
        int iy = n / 3 - 1, ix = n % 3 - 1;
        int yn = y0 + iy * dil, xn = x0 + ix * dil;
        bool ok = ((unsigned)yn < 64u) && ((unsigned)xn < 64u);
        int npix = ok ? (yn * 64 + xn) : pix;       // safe address for OOB
        offs[n] = (uint32_t)npix * (CH * 2);
        okm |= (unsigned)ok << n;
        uint4 kr = *reinterpret_cast<const uint4*>(kb + offs[n]);
        __half2 acc = __hmul2(q2[0], *reinterpret_cast<__half2*>(&kr.x));
        acc = __hfma2(q2[1], *reinterpret_cast<__half2*>(&kr.y), acc);
        acc = __hfma2(q2[2], *reinterpret_cast<__half2*>(&kr.z), acc);
        acc = __hfma2(q2[3], *reinterpret_cast<__half2*>(&kr.w), acc);
        float2 f = __half22float2(acc);
        float d = f.x + f.y;
        d += __shfl_xor_sync(0xffffffffu, d, 1);
        d += __shfl_xor_sync(0xffffffffu, d, 2);
        d += __shfl_xor_sync(0xffffffffu, d, 4);
        logit[n] = ok ? d * 0.125f : 0.f;   // SCALE = 64^-0.5; OOB taps -> logit 0 (zero-padded k)
    }

    // ---- softmax (normalization folded into weights) ----
    float m = logit[0];
#pragma unroll
    for (int n = 1; n < 9; n++) m = fmaxf(m, logit[n]);
    float p[9], den = 0.f;
#pragma unroll
    for (int n = 0; n < 9; n++) {
        p[n] = __expf(logit[n] - m);
        den += p[n];                         // zero-padded taps contribute exp(0-m)
    }
    float inv = 1.f / den;
    __half2 pw[9];
#pragma unroll
    for (int n = 0; n < 9; n++)
        pw[n] = __float2half2_rn(((okm >> n) & 1u) ? p[n] * inv : 0.f);   // normalized; OOB V weight 0

    // ---- pass 2: branchless fp16 V accumulation (already normalized) ----
    __half2 ac[4];
    ac[0] = __floats2half2_rn(0.f, 0.f);
    ac[1] = ac[0]; ac[2] = ac[0]; ac[3] = ac[0];
#pragma unroll
    for (int n = 0; n < 9; n++) {
        uint4 vr = *reinterpret_cast<const uint4*>(vb + offs[n]);
        ac[0] = __hfma2(pw[n], *reinterpret_cast<__half2*>(&vr.x), ac[0]);
        ac[1] = __hfma2(pw[n], *reinterpret_cast<__half2*>(&vr.y), ac[1]);
        ac[2] = __hfma2(pw[n], *reinterpret_cast<__half2*>(&vr.z), ac[2]);
        ac[3] = __hfma2(pw[n], *reinterpret_cast<__half2*>(&vr.w), ac[3]);
    }

    // ---- store 8 halves ----
    int G  = pix * 2 + head;
    int F2 = (G >> 6) * 12288 + (G & 63) * 192 + di * 64;
    uint4 ov;
    uint32_t* ovp = reinterpret_cast<uint32_t*>(&ov);
#pragma unroll
    for (int i = 0; i < 4; i++)
        ovp[i] = *reinterpret_cast<uint32_t*>(&ac[i]);
    *reinterpret_cast<uint4*>(aa.o[sel] + (size_t)b * HWPIX * CH + F2 + g * 8) = ov;
}

// ==================== launch ====================
extern "C" void kernel_launch(void* const* d_in, const int* in_sizes, int n_in,
                              void* d_out, int out_size)
{
    const float* vi  = (const float*)d_in[0];
    const float* ir  = (const float*)d_in[1];
    const float* gvi = (const float*)d_in[2];
    const float* bvi = (const float*)d_in[3];
    const float* gir = (const float*)d_in[4];
    const float* bir = (const float*)d_in[5];
    const float* wq1 = (const float*)d_in[6];
    const float* bq1 = (const float*)d_in[7];
    const float* wk1 = (const float*)d_in[8];
    const float* bk1 = (const float*)d_in[9];
    const float* wv1 = (const float*)d_in[10];
    const float* bv1 = (const float*)d_in[11];
    const float* wp1 = (const float*)d_in[12];
    const float* bp1 = (const float*)d_in[13];
    const float* wq2 = (const float*)d_in[14];
    const float* bq2 = (const float*)d_in[15];
    const float* wk2 = (const float*)d_in[16];
    const float* bk2 = (const float*)d_in[17];
    const float* wv2 = (const float*)d_in[18];
    const float* bv2 = (const float*)d_in[19];
    const float* wp2 = (const float*)d_in[20];
    const float* bp2 = (const float*)d_in[21];
    float* out = (float*)d_out;

    __half *p_vifh, *p_irfh, *p_s1h, *p_axh, *p_axh2, *p_wh;
    __half *p_q1, *p_k1, *p_v1, *p_q2, *p_k2, *p_v2;
    float  *p_s1n;
    cudaGetSymbolAddress((void**)&p_vifh, g_vifh);
    cudaGetSymbolAddress((void**)&p_irfh, g_irfh);
    cudaGetSymbolAddress((void**)&p_s1h,  g_s1h);
    cudaGetSymbolAddress((void**)&p_axh,  g_axh);
    cudaGetSymbolAddress((void**)&p_axh2, g_axh2);
    cudaGetSymbolAddress((void**)&p_wh,   g_wh);
    cudaGetSymbolAddress((void**)&p_s1n,  g_s1n);
    cudaGetSymbolAddress((void**)&p_q1,   g_q1);
    cudaGetSymbolAddress((void**)&p_k1,   g_k1);
    cudaGetSymbolAddress((void**)&p_v1,   g_v1);
    cudaGetSymbolAddress((void**)&p_q2,   g_q2);
    cudaGetSymbolAddress((void**)&p_k2,   g_k2);
    cudaGetSymbolAddress((void**)&p_v2,   g_v2);

    cudaFuncSetAttribute(gemm_tc_kernel<0>, cudaFuncAttributeMaxDynamicSharedMemorySize, SM_TOTAL);
    cudaFuncSetAttribute(gemm_tc_kernel<1>, cudaFuncAttributeMaxDynamicSharedMemorySize, SM_TOTAL);
    cudaFuncSetAttribute(ln_fused_kernel,   cudaFuncAttributeMaxDynamicSharedMemorySize, LN_SMEM);

    // weights -> fp16 (order: wq1,wk1,wv1,wp1,wq2,wk2,wv2,wp2)
    WPtrs wp;
    wp.w[0] = wq1; wp.w[1] = wk1; wp.w[2] = wv1; wp.w[3] = wp1;
    wp.w[4] = wq2; wp.w[5] = wk2; wp.w[6] = wv2; wp.w[7] = wp2;
    convw_kernel<<<dim3(144, 8), 256>>>(wp);

    ln_fused_kernel<<<ROWS / LNP, 256, LN_SMEM>>>(vi, ir, gvi, bvi, gir, bir);

    // ---- all six pre-attention GEMMs in one launch (R11 proven config) ----
    BatchArgs qkv = {};
    qkv.X[0] = p_s1h;  qkv.W[0] = p_wh + 0*WELEMS; qkv.bias[0] = bq1; qkv.Y[0] = p_q1; qkv.alpha[0] =  1.f;
    qkv.X[1] = p_vifh; qkv.W[1] = p_wh + 1*WELEMS; qkv.bias[1] = bk1; qkv.Y[1] = p_k1; qkv.alpha[1] =  1.f;
    qkv.X[2] = p_vifh; qkv.W[2] = p_wh + 2*WELEMS; qkv.bias[2] = bv1; qkv.Y[2] = p_v1; qkv.alpha[2] =  1.f;
    qkv.X[3] = p_s1h;  qkv.W[3] = p_wh + 4*WELEMS; qkv.bias[3] = bq2; qkv.Y[3] = p_q2; qkv.alpha[3] = -1.f;
    qkv.X[4] = p_irfh; qkv.W[4] = p_wh + 5*WELEMS; qkv.bias[4] = bk2; qkv.Y[4] = p_k2; qkv.alpha[4] =  1.f;
    qkv.X[5] = p_irfh; qkv.W[5] = p_wh + 6*WELEMS; qkv.bias[5] = bv2; qkv.Y[5] = p_v2; qkv.alpha[5] =  1.f;
    gemm_tc_kernel<0><<<dim3(ROWS/128, CH/128, 6), 256, SM_TOTAL>>>(qkv);

    // ---- both attentions in one launch (4 units/warp) ----
    AttnArgs aa;
    aa.q[0] = p_q1; aa.k[0] = p_k1; aa.v[0] = p_v1; aa.o[0] = p_axh;
    aa.q[1] = p_q2; aa.k[1] = p_k2; aa.v[1] = p_v2; aa.o[1] = p_axh2;
    attn_kernel<<<6144, 256>>>(aa);

    // ---- both projections (+ residual, NCHW scatter) in one launch ----
    BatchArgs pj = {};
    pj.X[0] = p_axh;  pj.W[0] = p_wh + 3*WELEMS; pj.bias[0] = bp1; pj.Y[0] = out;                      pj.alpha[0] = 1.f; pj.ssign[0] =  1.f;
    pj.X[1] = p_axh2; pj.W[1] = p_wh + 7*WELEMS; pj.bias[1] = bp2; pj.Y[1] = out + (size_t)ROWS * CH;  pj.alpha[1] = 1.f; pj.ssign[1] = -1.f;
    pj.S = p_s1n;
    gemm_tc_kernel<1><<<dim3(ROWS/128, CH/128, 2), 256, SM_TOTAL>>>(pj);
}

// round 16
// speedup vs baseline: 1.0686x; 1.0312x over previous
#include <cuda_runtime.h>
#include <cuda_fp16.h>
#include <cstdint>

#define BATCH 4
#define CH    384
#define HWPIX 4096
#define ROWS  (BATCH*HWPIX)      // 16384
#define WELEMS (CH*CH)           // 147456
#define NCONVB 1152              // weight-conversion blocks in merged launch

// -------- scratch (static device globals; no allocation allowed) --------
__device__ __align__(16) __half g_vifh[ROWS*CH];
__device__ __align__(16) __half g_irfh[ROWS*CH];
__device__ __align__(16) __half g_s1h [ROWS*CH];
__device__ __align__(16) __half g_axh [ROWS*CH];
__device__ __align__(16) __half g_axh2[ROWS*CH];
__device__ __align__(16) float  g_s1n [ROWS*CH];   // s1 in NCHW (for residual epilogue)
__device__ __align__(16) __half g_q1  [ROWS*CH];
__device__ __align__(16) __half g_k1  [ROWS*CH];
__device__ __align__(16) __half g_v1  [ROWS*CH];
__device__ __align__(16) __half g_q2  [ROWS*CH];
__device__ __align__(16) __half g_k2  [ROWS*CH];
__device__ __align__(16) __half g_v2  [ROWS*CH];
__device__ __align__(16) __half g_wh  [8*WELEMS];  // fp16 weights

// ==================== PTX helpers (base sm_103-safe) ====================
__device__ __forceinline__ uint32_t smem_u32(const void* p) {
    uint32_t a;
    asm("{ .reg .u64 t; cvta.to.shared.u64 t, %1; cvt.u32.u64 %0, t; }" : "=r"(a) : "l"(p));
    return a;
}

__device__ __forceinline__ void ldm4(uint32_t* r, uint32_t addr) {
    asm volatile("ldmatrix.sync.aligned.m8n8.x4.shared.b16 {%0,%1,%2,%3}, [%4];"
        : "=r"(r[0]), "=r"(r[1]), "=r"(r[2]), "=r"(r[3]) : "r"(addr));
}

__device__ __forceinline__ void mma16816(float* c, const uint32_t* a, uint32_t b0, uint32_t b1) {
    asm volatile("mma.sync.aligned.m16n8k16.row.col.f32.f16.f16.f32 "
        "{%0,%1,%2,%3}, {%4,%5,%6,%7}, {%8,%9}, {%0,%1,%2,%3};"
        : "+f"(c[0]), "+f"(c[1]), "+f"(c[2]), "+f"(c[3])
        : "r"(a[0]), "r"(a[1]), "r"(a[2]), "r"(a[3]), "r"(b0), "r"(b1));
}

__device__ __forceinline__ void cpasync16(uint32_t saddr, const void* gaddr) {
    asm volatile("cp.async.cg.shared.global [%0], [%1], 16;" :: "r"(saddr), "l"(gaddr));
}
#define CP_COMMIT() asm volatile("cp.async.commit_group;" ::: "memory")
template<int N> __device__ __forceinline__ void cp_wait() {
    asm volatile("cp.async.wait_group %0;" :: "n"(N) : "memory");
}

// ==================== merged weight-convert + fused LayerNorm ====================
// Blocks [0, NCONVB): fp32->fp16 weight conversion (8 matrices).
// Blocks [NCONVB, NCONVB+1024): single-pass LN over 16 pixels each.
struct WPtrs { const float* w[8]; };

#define LNP 16
#define LNS 17
#define LN_ARR (CH*LNS)            // 6528 floats per array
#define LN_SMEM (2*LN_ARR*4)       // 52224 bytes dynamic

__global__ __launch_bounds__(256) void ln_conv_kernel(WPtrs wp,
    const float* __restrict__ vi, const float* __restrict__ ir,
    const float* __restrict__ gvi, const float* __restrict__ bvi,
    const float* __restrict__ gir, const float* __restrict__ bir)
{
    int tid = threadIdx.x;

    if (blockIdx.x < NCONVB) {
        // ---- weight conversion path ----
        int bx = blockIdx.x;
        int m = bx / 144;
        int i = ((bx - m * 144) * 256 + tid) * 4;
        float4 v = *reinterpret_cast<const float4*>(wp.w[m] + i);
        __half2 h0 = __floats2half2_rn(v.x, v.y);
        __half2 h1 = __floats2half2_rn(v.z, v.w);
        uint2 pk;
        pk.x = *reinterpret_cast<uint32_t*>(&h0);
        pk.y = *reinterpret_cast<uint32_t*>(&h1);
        *reinterpret_cast<uint2*>(g_wh + (size_t)m * WELEMS + i) = pk;
        return;
    }

    // ---- LN path ----
    extern __shared__ float dsm[];
    float* sva = dsm;               // [384][17]
    float* sve = dsm + LN_ARR;
    __shared__ float sgv[CH], sbv[CH], sgi[CH], sbi[CH];
    __shared__ float red[256][4];
    __shared__ float4 stat[LNP];

    int pix0 = (blockIdx.x - NCONVB) * LNP;
    int b = pix0 >> 12, p0 = pix0 & 4095;

    for (int i = tid; i < CH; i += 256) {
        sgv[i] = gvi[i]; sbv[i] = bvi[i];
        sgi[i] = gir[i]; sbi[i] = bir[i];
    }

    int pl = tid & 15, cb = tid >> 4;
    const float* basev = vi + (((size_t)b * CH) << 12) + p0 + pl;
    const float* basei = ir + (((size_t)b * CH) << 12) + p0 + pl;
#pragma unroll
    for (int it = 0; it < 24; it++) {
        int c = cb + it * 16;
        sva[c * LNS + pl] = basev[(size_t)c << 12];
        sve[c * LNS + pl] = basei[(size_t)c << 12];
    }
    __syncthreads();

    float s1 = 0.f, s2 = 0.f, s3 = 0.f, s4 = 0.f;
#pragma unroll
    for (int j = 0; j < 24; j++) {
        int c = cb * 24 + j;
        float a = sva[c * LNS + pl];
        float e = sve[c * LNS + pl];
        s1 += a; s2 += a * a; s3 += e; s4 += e * e;
    }
    red[tid][0] = s1; red[tid][1] = s2; red[tid][2] = s3; red[tid][3] = s4;
    __syncthreads();
    if (tid < LNP) {
        float a = 0.f, q = 0.f, e = 0.f, r = 0.f;
#pragma unroll
        for (int s = 0; s < 16; s++) {
            a += red[s * 16 + tid][0]; q += red[s * 16 + tid][1];
            e += red[s * 16 + tid][2]; r += red[s * 16 + tid][3];
        }
        float ma = a * (1.f/CH), me = e * (1.f/CH);
        float va = q * (1.f/CH) - ma * ma;
        float ve = r * (1.f/CH) - me * me;
        float4 st;
        st.x = ma; st.y = rsqrtf(va + 1e-6f);
        st.z = me; st.w = rsqrtf(ve + 1e-6f);
        stat[tid] = st;
    }
    __syncthreads();

    int w = tid >> 5, lane = tid & 31;
#pragma unroll
    for (int pp = 0; pp < 2; pp++) {
        int p = w * 2 + pp;
        float4 st = stat[p];
        size_t rb = (size_t)(pix0 + p) * CH;
#pragma unroll
        for (int j = 0; j < 6; j++) {
            int c = j * 64 + lane * 2;
            float a0 = sva[c * LNS + p], a1 = sva[(c + 1) * LNS + p];
            float e0 = sve[c * LNS + p], e1 = sve[(c + 1) * LNS + p];
            float fv0 = (a0 - st.x) * st.y * sgv[c]     + sbv[c];
            float fv1 = (a1 - st.x) * st.y * sgv[c + 1] + sbv[c + 1];
            float fi0 = (e0 - st.z) * st.w * sgi[c]     + sbi[c];
            float fi1 = (e1 - st.z) * st.w * sgi[c + 1] + sbi[c + 1];
            *reinterpret_cast<__half2*>(g_vifh + rb + c) = __floats2half2_rn(fv0, fv1);
            *reinterpret_cast<__half2*>(g_irfh + rb + c) = __floats2half2_rn(fi0, fi1);
            *reinterpret_cast<__half2*>(g_s1h  + rb + c) = __floats2half2_rn(fv0 - fi0, fv1 - fi1);
        }
    }

    float4 stp = stat[pl];
#pragma unroll
    for (int it = 0; it < 24; it++) {
        int c = cb + it * 16;
        float a = sva[c * LNS + pl], e = sve[c * LNS + pl];
        float fv = (a - stp.x) * stp.y * sgv[c] + sbv[c];
        float fi = (e - stp.z) * stp.w * sgi[c] + sbi[c];
        g_s1n[(((size_t)(b * CH + c)) << 12) + p0 + pl] = fv - fi;
    }
}

// ==================== pipelined HMMA GEMM (z-batched) — R11/R13 proven config ====================
#define KC      64
#define CRS     72                        // chunk row stride (halves)
#define STAGE_A_BYTES (128*CRS*2)         // 18432
#define STAGE_BYTES   (2*STAGE_A_BYTES)   // 36864
#define NSTAGE  3
#define SM_TOTAL (NSTAGE*STAGE_BYTES)     // 110592
#define STG_RS  129                       // MODE1 staging stride (floats)

struct BatchArgs {
    const __half* X[6];
    const __half* W[6];
    const float*  bias[6];
    void*         Y[6];
    float         alpha[6];
    const float*  S;
    float         ssign[6];
};

template<int MODE>
__global__ __launch_bounds__(256, 2) void gemm_tc_kernel(BatchArgs ba)
{
    extern __shared__ char smem[];
    __shared__ float sbias[128];
    uint32_t sbA = smem_u32(smem);
    int z = blockIdx.z;
    const __half* __restrict__ X = ba.X[z];
    const __half* __restrict__ W = ba.W[z];
    float alpha = ba.alpha[z];

    int tid = threadIdx.x, wid = tid >> 5, lane = tid & 31;
    int r0 = blockIdx.x * 128, o0 = blockIdx.y * 128;
    int mw0 = (wid & 3) * 32;            // warp M origin
    int nw0 = (wid >> 2) * 64;           // warp N origin

    if (tid < 128) sbias[tid] = ba.bias[z][o0 + tid];

    int lrow = tid >> 3;
    int lch  = tid & 7;
    const __half* gA = X + (size_t)r0 * CH;
    const __half* gB = W + (size_t)o0 * CH;

    auto load_chunk = [&](int c, int s) {
        uint32_t sbase = sbA + s * STAGE_BYTES;
        int kof = c * KC + lch * 8;
#pragma unroll
        for (int it = 0; it < 4; it++) {
            int row = lrow + it * 32;
            cpasync16(sbase + (uint32_t)((row * CRS + lch * 8) * 2),
                      gA + (size_t)row * CH + kof);
        }
#pragma unroll
        for (int it = 0; it < 4; it++) {
            int row = lrow + it * 32;
            cpasync16(sbase + STAGE_A_BYTES + (uint32_t)((row * CRS + lch * 8) * 2),
                      gB + (size_t)row * CH + kof);
        }
    };

    uint32_t aOff = (uint32_t)(((mw0 + (lane & 15)) * CRS + (lane >> 4) * 8) * 2);
    uint32_t bOff = (uint32_t)(STAGE_A_BYTES +
                    ((nw0 + ((lane >> 4) * 8 + (lane & 7))) * CRS + ((lane >> 3) & 1) * 8) * 2);

    float c[2][8][4];
#pragma unroll
    for (int i = 0; i < 2; i++)
#pragma unroll
        for (int j = 0; j < 8; j++)
#pragma unroll
            for (int q = 0; q < 4; q++) c[i][j][q] = 0.f;

    auto compute = [&](int s) {
        uint32_t aB = sbA + s * STAGE_BYTES + aOff;
        uint32_t bB = sbA + s * STAGE_BYTES + bOff;
#pragma unroll
        for (int ks = 0; ks < 4; ks++) {
            uint32_t a[2][4], b[4][4];
            ldm4(a[0], aB + ks * 32);
            ldm4(a[1], aB + ks * 32 + 16 * CRS * 2);
#pragma unroll
            for (int g = 0; g < 4; g++)
                ldm4(b[g], bB + ks * 32 + g * 16 * CRS * 2);
#pragma unroll
            for (int i = 0; i < 2; i++)
#pragma unroll
                for (int j = 0; j < 8; j++) {
                    const uint32_t* bg = b[j >> 1];
                    uint32_t b0 = (j & 1) ? bg[2] : bg[0];
                    uint32_t b1 = (j & 1) ? bg[3] : bg[1];
                    mma16816(c[i][j], a[i], b0, b1);
                }
        }
    };

    load_chunk(0, 0); CP_COMMIT();
    load_chunk(1, 1); CP_COMMIT();
#pragma unroll
    for (int cc = 0; cc < 6; cc++) {
        if (cc < 5) cp_wait<1>(); else cp_wait<0>();
        __syncthreads();
        if (cc < 4) { load_chunk(cc + 2, (cc + 2) % NSTAGE); CP_COMMIT(); }
        compute(cc % NSTAGE);
    }

    int tq = lane >> 2, tr = lane & 3;

    if (MODE == 0) {
        __half* Y = reinterpret_cast<__half*>(ba.Y[z]);
#pragma unroll
        for (int i = 0; i < 2; i++)
#pragma unroll
            for (int j = 0; j < 8; j++) {
                int colb = nw0 + j * 8 + tr * 2;
#pragma unroll
                for (int h = 0; h < 2; h++) {
                    int row = r0 + mw0 + i * 16 + tq + h * 8;
                    __half2 hv = __floats2half2_rn(
                        alpha * c[i][j][h * 2 + 0] + sbias[colb],
                        alpha * c[i][j][h * 2 + 1] + sbias[colb + 1]);
                    *reinterpret_cast<__half2*>(Y + (size_t)row * CH + o0 + colb) = hv;
                }
            }
    } else {
        float* Y = reinterpret_cast<float*>(ba.Y[z]);
        const float* S = ba.S;
        float ssign = ba.ssign[z];
        float* smemf = reinterpret_cast<float*>(smem);
        __syncthreads();
#pragma unroll
        for (int i = 0; i < 2; i++)
#pragma unroll
            for (int j = 0; j < 8; j++) {
                int colb = nw0 + j * 8 + tr * 2;
#pragma unroll
                for (int h = 0; h < 2; h++) {
                    int row = mw0 + i * 16 + tq + h * 8;
                    smemf[row * STG_RS + colb]     = c[i][j][h * 2 + 0];
                    smemf[row * STG_RS + colb + 1] = c[i][j][h * 2 + 1];
                }
            }
        __syncthreads();
        int b = r0 >> 12, p0r = r0 & 4095;
        for (int tk = wid * 64; tk < wid * 64 + 64; tk++) {
            int col = tk >> 2, rb = tk & 3;
            int row = rb * 32 + lane;
            float val = smemf[row * STG_RS + col];
            size_t addr = (((size_t)(b * CH + o0 + col)) << 12) + p0r + row;
            Y[addr] = val + sbias[col] + ssign * S[addr];
        }
    }
}

// ==================== dilated 3x3 window attention — exact R13 config ====================
// 4 units/warp, 8 lanes/unit; lane owns 8 contiguous head-dims.
// Offsets cached from pass 1 (OOB -> safe own-pixel addr, weight 0);
// pass 2 branchless fp16 hfma2 accumulation; normalization fp32 at end.
struct AttnArgs {
    const __half* q[2]; const __half* k[2]; const __half* v[2]; __half* o[2];
};

__global__ __launch_bounds__(256) void attn_kernel(AttnArgs aa)
{
    int tid  = threadIdx.x;
    int wid  = tid >> 5, lane = tid & 31;
    int g    = lane & 7;                       // lane within unit group
    int u    = blockIdx.x * 32 + wid * 4 + (lane >> 3);   // 0..196607
    int sel  = u >= 98304;
    int unit = u - sel * 98304;

    int pix  = unit & 4095;
    int t    = unit >> 12;
    int head = t & 1;  t >>= 1;
    int di   = t % 3;
    int b    = t / 3;
    int dil  = di + 1;
    int y0   = pix >> 6, x0 = pix & 63;
    int chan = di * 128 + head * 64;

    size_t sbase = (size_t)b * HWPIX * CH + chan + g * 8;  // lane's 8-dim slice
    const char* kb = reinterpret_cast<const char*>(aa.k[sel] + sbase);
    const char* vb = reinterpret_cast<const char*>(aa.v[sel] + sbase);

    uint4 qr = *reinterpret_cast<const uint4*>(aa.q[sel] + sbase + (size_t)pix * CH);
    __half2 q2[4];
    q2[0] = *reinterpret_cast<__half2*>(&qr.x);
    q2[1] = *reinterpret_cast<__half2*>(&qr.y);
    q2[2] = *reinterpret_cast<__half2*>(&qr.z);
    q2[3] = *reinterpret_cast<__half2*>(&qr.w);

    // ---- pass 1: logits + cached offsets ----
    uint32_t offs[9];
    float logit[9];
    unsigned okm = 0;
#pragma unroll
    for (int n = 0; n < 9; n++) {
        int iy = n / 3 - 1, ix = n % 3 - 1;
        int yn = y0 + iy * dil, xn = x0 + ix * dil;
        bool ok = ((unsigned)yn < 64u) && ((unsigned)xn < 64u);
        int npix = ok ? (yn * 64 + xn) : pix;       // safe address for OOB
        offs[n] = (uint32_t)npix * (CH * 2);
        okm |= (unsigned)ok << n;
        uint4 kr = *reinterpret_cast<const uint4*>(kb + offs[n]);
        __half2 acc = __hmul2(q2[0], *reinterpret_cast<__half2*>(&kr.x));
        acc = __hfma2(q2[1], *reinterpret_cast<__half2*>(&kr.y), acc);
        acc = __hfma2(q2[2], *reinterpret_cast<__half2*>(&kr.z), acc);
        acc = __hfma2(q2[3], *reinterpret_cast<__half2*>(&kr.w), acc);
        float2 f = __half22float2(acc);
        float d = f.x + f.y;
        d += __shfl_xor_sync(0xffffffffu, d, 1);
        d += __shfl_xor_sync(0xffffffffu, d, 2);
        d += __shfl_xor_sync(0xffffffffu, d, 4);
        logit[n] = ok ? d * 0.125f : 0.f;   // SCALE = 64^-0.5; OOB taps -> logit 0 (zero-padded k)
    }

    // ---- softmax ----
    float m = logit[0];
#pragma unroll
    for (int n = 1; n < 9; n++) m = fmaxf(m, logit[n]);
    float den = 0.f;
    __half2 pw[9];
#pragma unroll
    for (int n = 0; n < 9; n++) {
        float p = __expf(logit[n] - m);
        den += p;                            // zero-padded taps contribute exp(0-m)
        pw[n] = __float2half2_rn(((okm >> n) & 1u) ? p : 0.f);   // weight 0 for OOB V
    }
    float inv = 1.f / den;

    // ---- pass 2: branchless fp16 V accumulation ----
    __half2 ac[4];
    ac[0] = __floats2half2_rn(0.f, 0.f);
    ac[1] = ac[0]; ac[2] = ac[0]; ac[3] = ac[0];
#pragma unroll
    for (int n = 0; n < 9; n++) {
        uint4 vr = *reinterpret_cast<const uint4*>(vb + offs[n]);
        ac[0] = __hfma2(pw[n], *reinterpret_cast<__half2*>(&vr.x), ac[0]);
        ac[1] = __hfma2(pw[n], *reinterpret_cast<__half2*>(&vr.y), ac[1]);
        ac[2] = __hfma2(pw[n], *reinterpret_cast<__half2*>(&vr.z), ac[2]);
        ac[3] = __hfma2(pw[n], *reinterpret_cast<__half2*>(&vr.w), ac[3]);
    }

    // ---- normalize (fp32) + store 8 halves ----
    int G  = pix * 2 + head;
    int F2 = (G >> 6) * 12288 + (G & 63) * 192 + di * 64;
    uint4 ov;
    uint32_t* ovp = reinterpret_cast<uint32_t*>(&ov);
#pragma unroll
    for (int i = 0; i < 4; i++) {
        float2 f = __half22float2(ac[i]);
        __half2 h = __floats2half2_rn(f.x * inv, f.y * inv);
        ovp[i] = *reinterpret_cast<uint32_t*>(&h);
    }
    *reinterpret_cast<uint4*>(aa.o[sel] + (size_t)b * HWPIX * CH + F2 + g * 8) = ov;
}

// ==================== launch ====================
extern "C" void kernel_launch(void* const* d_in, const int* in_sizes, int n_in,
                              void* d_out, int out_size)
{
    const float* vi  = (const float*)d_in[0];
    const float* ir  = (const float*)d_in[1];
    const float* gvi = (const float*)d_in[2];
    const float* bvi = (const float*)d_in[3];
    const float* gir = (const float*)d_in[4];
    const float* bir = (const float*)d_in[5];
    const float* wq1 = (const float*)d_in[6];
    const float* bq1 = (const float*)d_in[7];
    const float* wk1 = (const float*)d_in[8];
    const float* bk1 = (const float*)d_in[9];
    const float* wv1 = (const float*)d_in[10];
    const float* bv1 = (const float*)d_in[11];
    const float* wp1 = (const float*)d_in[12];
    const float* bp1 = (const float*)d_in[13];
    const float* wq2 = (const float*)d_in[14];
    const float* bq2 = (const float*)d_in[15];
    const float* wk2 = (const float*)d_in[16];
    const float* bk2 = (const float*)d_in[17];
    const float* wv2 = (const float*)d_in[18];
    const float* bv2 = (const float*)d_in[19];
    const float* wp2 = (const float*)d_in[20];
    const float* bp2 = (const float*)d_in[21];
    float* out = (float*)d_out;

    __half *p_vifh, *p_irfh, *p_s1h, *p_axh, *p_axh2, *p_wh;
    __half *p_q1, *p_k1, *p_v1, *p_q2, *p_k2, *p_v2;
    float  *p_s1n;
    cudaGetSymbolAddress((void**)&p_vifh, g_vifh);
    cudaGetSymbolAddress((void**)&p_irfh, g_irfh);
    cudaGetSymbolAddress((void**)&p_s1h,  g_s1h);
    cudaGetSymbolAddress((void**)&p_axh,  g_axh);
    cudaGetSymbolAddress((void**)&p_axh2, g_axh2);
    cudaGetSymbolAddress((void**)&p_wh,   g_wh);
    cudaGetSymbolAddress((void**)&p_s1n,  g_s1n);
    cudaGetSymbolAddress((void**)&p_q1,   g_q1);
    cudaGetSymbolAddress((void**)&p_k1,   g_k1);
    cudaGetSymbolAddress((void**)&p_v1,   g_v1);
    cudaGetSymbolAddress((void**)&p_q2,   g_q2);
    cudaGetSymbolAddress((void**)&p_k2,   g_k2);
    cudaGetSymbolAddress((void**)&p_v2,   g_v2);

    cudaFuncSetAttribute(gemm_tc_kernel<0>, cudaFuncAttributeMaxDynamicSharedMemorySize, SM_TOTAL);
    cudaFuncSetAttribute(gemm_tc_kernel<1>, cudaFuncAttributeMaxDynamicSharedMemorySize, SM_TOTAL);
    cudaFuncSetAttribute(ln_conv_kernel,    cudaFuncAttributeMaxDynamicSharedMemorySize, LN_SMEM);

    // merged: weight fp16 conversion (blocks 0..1151) + LN (blocks 1152..2175)
    WPtrs wp;
    wp.w[0] = wq1; wp.w[1] = wk1; wp.w[2] = wv1; wp.w[3] = wp1;
    wp.w[4] = wq2; wp.w[5] = wk2; wp.w[6] = wv2; wp.w[7] = wp2;
    ln_conv_kernel<<<NCONVB + ROWS / LNP, 256, LN_SMEM>>>(wp, vi, ir, gvi, bvi, gir, bir);

    // ---- all six pre-attention GEMMs in one launch (R11 proven config) ----
    BatchArgs qkv = {};
    qkv.X[0] = p_s1h;  qkv.W[0] = p_wh + 0*WELEMS; qkv.bias[0] = bq1; qkv.Y[0] = p_q1; qkv.alpha[0] =  1.f;
    qkv.X[1] = p_vifh; qkv.W[1] = p_wh + 1*WELEMS; qkv.bias[1] = bk1; qkv.Y[1] = p_k1; qkv.alpha[1] =  1.f;
    qkv.X[2] = p_vifh; qkv.W[2] = p_wh + 2*WELEMS; qkv.bias[2] = bv1; qkv.Y[2] = p_v1; qkv.alpha[2] =  1.f;
    qkv.X[3] = p_s1h;  qkv.W[3] = p_wh + 4*WELEMS; qkv.bias[3] = bq2; qkv.Y[3] = p_q2; qkv.alpha[3] = -1.f;
    qkv.X[4] = p_irfh; qkv.W[4] = p_wh + 5*WELEMS; qkv.bias[4] = bk2; qkv.Y[4] = p_k2; qkv.alpha[4] =  1.f;
    qkv.X[5] = p_irfh; qkv.W[5] = p_wh + 6*WELEMS; qkv.bias[5] = bv2; qkv.Y[5] = p_v2; qkv.alpha[5] =  1.f;
    gemm_tc_kernel<0><<<dim3(ROWS/128, CH/128, 6), 256, SM_TOTAL>>>(qkv);

    // ---- both attentions in one launch (4 units/warp) ----
    AttnArgs aa;
    aa.q[0] = p_q1; aa.k[0] = p_k1; aa.v[0] = p_v1; aa.o[0] = p_axh;
    aa.q[1] = p_q2; aa.k[1] = p_k2; aa.v[1] = p_v2; aa.o[1] = p_axh2;
    attn_kernel<<<6144, 256>>>(aa);

    // ---- both projections (+ residual, NCHW scatter) in one launch ----
    BatchArgs pj = {};
    pj.X[0] = p_axh;  pj.W[0] = p_wh + 3*WELEMS; pj.bias[0] = bp1; pj.Y[0] = out;                      pj.alpha[0] = 1.f; pj.ssign[0] =  1.f;
    pj.X[1] = p_axh2; pj.W[1] = p_wh + 7*WELEMS; pj.bias[1] = bp2; pj.Y[1] = out + (size_t)ROWS * CH;  pj.alpha[1] = 1.f; pj.ssign[1] = -1.f;
    pj.S = p_s1n;
    gemm_tc_kernel<1><<<dim3(ROWS/128, CH/128, 2), 256, SM_TOTAL>>>(pj);
}

// round 17
// speedup vs baseline: 1.3023x; 1.2187x over previous
#include <cuda_runtime.h>
#include <cuda_fp16.h>
#include <cstdint>

#define BATCH 4
#define CH    384
#define HWPIX 4096
#define ROWS  (BATCH*HWPIX)      // 16384
#define WELEMS (CH*CH)           // 147456
#define NCONVB 1152              // weight-conversion blocks in merged launch

// -------- scratch (static device globals; no allocation allowed) --------
__device__ __align__(16) __half g_vifh[ROWS*CH];
__device__ __align__(16) __half g_irfh[ROWS*CH];
__device__ __align__(16) __half g_s1h [ROWS*CH];
__device__ __align__(16) __half g_axh [ROWS*CH];
__device__ __align__(16) __half g_axh2[ROWS*CH];
__device__ __align__(16) float  g_s1n [ROWS*CH];   // s1 in NCHW (for residual epilogue)
__device__ __align__(16) __half g_q1  [ROWS*CH];
__device__ __align__(16) __half g_k1  [ROWS*CH];
__device__ __align__(16) __half g_v1  [ROWS*CH];
__device__ __align__(16) __half g_q2  [ROWS*CH];
__device__ __align__(16) __half g_k2  [ROWS*CH];
__device__ __align__(16) __half g_v2  [ROWS*CH];
__device__ __align__(16) __half g_wh  [8*WELEMS];  // fp16 weights

// ==================== PTX helpers (base sm_103-safe) ====================
__device__ __forceinline__ uint32_t smem_u32(const void* p) {
    uint32_t a;
    asm("{ .reg .u64 t; cvta.to.shared.u64 t, %1; cvt.u32.u64 %0, t; }" : "=r"(a) : "l"(p));
    return a;
}

__device__ __forceinline__ void ldm4(uint32_t* r, uint32_t addr) {
    asm volatile("ldmatrix.sync.aligned.m8n8.x4.shared.b16 {%0,%1,%2,%3}, [%4];"
        : "=r"(r[0]), "=r"(r[1]), "=r"(r[2]), "=r"(r[3]) : "r"(addr));
}

__device__ __forceinline__ void mma16816(float* c, const uint32_t* a, uint32_t b0, uint32_t b1) {
    asm volatile("mma.sync.aligned.m16n8k16.row.col.f32.f16.f16.f32 "
        "{%0,%1,%2,%3}, {%4,%5,%6,%7}, {%8,%9}, {%0,%1,%2,%3};"
        : "+f"(c[0]), "+f"(c[1]), "+f"(c[2]), "+f"(c[3])
        : "r"(a[0]), "r"(a[1]), "r"(a[2]), "r"(a[3]), "r"(b0), "r"(b1));
}

__device__ __forceinline__ void cpasync16(uint32_t saddr, const void* gaddr) {
    asm volatile("cp.async.cg.shared.global [%0], [%1], 16;" :: "r"(saddr), "l"(gaddr));
}
#define CP_COMMIT() asm volatile("cp.async.commit_group;" ::: "memory")
template<int N> __device__ __forceinline__ void cp_wait() {
    asm volatile("cp.async.wait_group %0;" :: "n"(N) : "memory");
}

// ==================== merged weight-convert + fused LayerNorm ====================
// Blocks [0, NCONVB): fp32->fp16 weight conversion (8 matrices).
// Blocks [NCONVB, NCONVB+1024): single-pass LN over 16 pixels each.
struct WPtrs { const float* w[8]; };

#define LNP 16
#define LNS 17
#define LN_ARR (CH*LNS)            // 6528 floats per array
#define LN_SMEM (2*LN_ARR*4)       // 52224 bytes dynamic

__global__ __launch_bounds__(256) void ln_conv_kernel(WPtrs wp,
    const float* __restrict__ vi, const float* __restrict__ ir,
    const float* __restrict__ gvi, const float* __restrict__ bvi,
    const float* __restrict__ gir, const float* __restrict__ bir)
{
    int tid = threadIdx.x;

    if (blockIdx.x < NCONVB) {
        // ---- weight conversion path ----
        int bx = blockIdx.x;
        int m = bx / 144;
        int i = ((bx - m * 144) * 256 + tid) * 4;
        float4 v = *reinterpret_cast<const float4*>(wp.w[m] + i);
        __half2 h0 = __floats2half2_rn(v.x, v.y);
        __half2 h1 = __floats2half2_rn(v.z, v.w);
        uint2 pk;
        pk.x = *reinterpret_cast<uint32_t*>(&h0);
        pk.y = *reinterpret_cast<uint32_t*>(&h1);
        *reinterpret_cast<uint2*>(g_wh + (size_t)m * WELEMS + i) = pk;
        return;
    }

    // ---- LN path ----
    extern __shared__ float dsm[];
    float* sva = dsm;               // [384][17]
    float* sve = dsm + LN_ARR;
    __shared__ float sgv[CH], sbv[CH], sgi[CH], sbi[CH];
    __shared__ float red[256][4];
    __shared__ float4 stat[LNP];

    int pix0 = (blockIdx.x - NCONVB) * LNP;
    int b = pix0 >> 12, p0 = pix0 & 4095;

    for (int i = tid; i < CH; i += 256) {
        sgv[i] = gvi[i]; sbv[i] = bvi[i];
        sgi[i] = gir[i]; sbi[i] = bir[i];
    }

    int pl = tid & 15, cb = tid >> 4;
    const float* basev = vi + (((size_t)b * CH) << 12) + p0 + pl;
    const float* basei = ir + (((size_t)b * CH) << 12) + p0 + pl;
#pragma unroll
    for (int it = 0; it < 24; it++) {
        int c = cb + it * 16;
        sva[c * LNS + pl] = basev[(size_t)c << 12];
        sve[c * LNS + pl] = basei[(size_t)c << 12];
    }
    __syncthreads();

    float s1 = 0.f, s2 = 0.f, s3 = 0.f, s4 = 0.f;
#pragma unroll
    for (int j = 0; j < 24; j++) {
        int c = cb * 24 + j;
        float a = sva[c * LNS + pl];
        float e = sve[c * LNS + pl];
        s1 += a; s2 += a * a; s3 += e; s4 += e * e;
    }
    red[tid][0] = s1; red[tid][1] = s2; red[tid][2] = s3; red[tid][3] = s4;
    __syncthreads();
    if (tid < LNP) {
        float a = 0.f, q = 0.f, e = 0.f, r = 0.f;
#pragma unroll
        for (int s = 0; s < 16; s++) {
            a += red[s * 16 + tid][0]; q += red[s * 16 + tid][1];
            e += red[s * 16 + tid][2]; r += red[s * 16 + tid][3];
        }
        float ma = a * (1.f/CH), me = e * (1.f/CH);
        float va = q * (1.f/CH) - ma * ma;
        float ve = r * (1.f/CH) - me * me;
        float4 st;
        st.x = ma; st.y = rsqrtf(va + 1e-6f);
        st.z = me; st.w = rsqrtf(ve + 1e-6f);
        stat[tid] = st;
    }
    __syncthreads();

    int w = tid >> 5, lane = tid & 31;
#pragma unroll
    for (int pp = 0; pp < 2; pp++) {
        int p = w * 2 + pp;
        float4 st = stat[p];
        size_t rb = (size_t)(pix0 + p) * CH;
#pragma unroll
        for (int j = 0; j < 6; j++) {
            int c = j * 64 + lane * 2;
            float a0 = sva[c * LNS + p], a1 = sva[(c + 1) * LNS + p];
            float e0 = sve[c * LNS + p], e1 = sve[(c + 1) * LNS + p];
            float fv0 = (a0 - st.x) * st.y * sgv[c]     + sbv[c];
            float fv1 = (a1 - st.x) * st.y * sgv[c + 1] + sbv[c + 1];
            float fi0 = (e0 - st.z) * st.w * sgi[c]     + sbi[c];
            float fi1 = (e1 - st.z) * st.w * sgi[c + 1] + sbi[c + 1];
            *reinterpret_cast<__half2*>(g_vifh + rb + c) = __floats2half2_rn(fv0, fv1);
            *reinterpret_cast<__half2*>(g_irfh + rb + c) = __floats2half2_rn(fi0, fi1);
            *reinterpret_cast<__half2*>(g_s1h  + rb + c) = __floats2half2_rn(fv0 - fi0, fv1 - fi1);
        }
    }

    float4 stp = stat[pl];
#pragma unroll
    for (int it = 0; it < 24; it++) {
        int c = cb + it * 16;
        float a = sva[c * LNS + pl], e = sve[c * LNS + pl];
        float fv = (a - stp.x) * stp.y * sgv[c] + sbv[c];
        float fi = (e - stp.z) * stp.w * sgi[c] + sbi[c];
        g_s1n[(((size_t)(b * CH + c)) << 12) + p0 + pl] = fv - fi;
    }
}

// ==================== pipelined HMMA GEMM (z-batched) — R11/R13 proven config ====================
#define KC      64
#define CRS     72                        // chunk row stride (halves)
#define STAGE_A_BYTES (128*CRS*2)         // 18432
#define STAGE_BYTES   (2*STAGE_A_BYTES)   // 36864
#define NSTAGE  3
#define SM_TOTAL (NSTAGE*STAGE_BYTES)     // 110592
#define SRS     132                       // MODE1 transposed staging stride (floats, [col][row])

struct BatchArgs {
    const __half* X[6];
    const __half* W[6];
    const float*  bias[6];
    void*         Y[6];
    float         alpha[6];
    const float*  S;
    float         ssign[6];
};

template<int MODE>
__global__ __launch_bounds__(256, 2) void gemm_tc_kernel(BatchArgs ba)
{
    extern __shared__ char smem[];
    __shared__ float sbias[128];
    uint32_t sbA = smem_u32(smem);
    int z = blockIdx.z;
    const __half* __restrict__ X = ba.X[z];
    const __half* __restrict__ W = ba.W[z];
    float alpha = ba.alpha[z];

    int tid = threadIdx.x, wid = tid >> 5, lane = tid & 31;
    int r0 = blockIdx.x * 128, o0 = blockIdx.y * 128;
    int mw0 = (wid & 3) * 32;            // warp M origin
    int nw0 = (wid >> 2) * 64;           // warp N origin

    if (tid < 128) sbias[tid] = ba.bias[z][o0 + tid];

    int lrow = tid >> 3;
    int lch  = tid & 7;
    const __half* gA = X + (size_t)r0 * CH;
    const __half* gB = W + (size_t)o0 * CH;

    auto load_chunk = [&](int c, int s) {
        uint32_t sbase = sbA + s * STAGE_BYTES;
        int kof = c * KC + lch * 8;
#pragma unroll
        for (int it = 0; it < 4; it++) {
            int row = lrow + it * 32;
            cpasync16(sbase + (uint32_t)((row * CRS + lch * 8) * 2),
                      gA + (size_t)row * CH + kof);
        }
#pragma unroll
        for (int it = 0; it < 4; it++) {
            int row = lrow + it * 32;
            cpasync16(sbase + STAGE_A_BYTES + (uint32_t)((row * CRS + lch * 8) * 2),
                      gB + (size_t)row * CH + kof);
        }
    };

    uint32_t aOff = (uint32_t)(((mw0 + (lane & 15)) * CRS + (lane >> 4) * 8) * 2);
    uint32_t bOff = (uint32_t)(STAGE_A_BYTES +
                    ((nw0 + ((lane >> 4) * 8 + (lane & 7))) * CRS + ((lane >> 3) & 1) * 8) * 2);

    float c[2][8][4];
#pragma unroll
    for (int i = 0; i < 2; i++)
#pragma unroll
        for (int j = 0; j < 8; j++)
#pragma unroll
            for (int q = 0; q < 4; q++) c[i][j][q] = 0.f;

    auto compute = [&](int s) {
        uint32_t aB = sbA + s * STAGE_BYTES + aOff;
        uint32_t bB = sbA + s * STAGE_BYTES + bOff;
#pragma unroll
        for (int ks = 0; ks < 4; ks++) {
            uint32_t a[2][4], b[4][4];
            ldm4(a[0], aB + ks * 32);
            ldm4(a[1], aB + ks * 32 + 16 * CRS * 2);
#pragma unroll
            for (int g = 0; g < 4; g++)
                ldm4(b[g], bB + ks * 32 + g * 16 * CRS * 2);
#pragma unroll
            for (int i = 0; i < 2; i++)
#pragma unroll
                for (int j = 0; j < 8; j++) {
                    const uint32_t* bg = b[j >> 1];
                    uint32_t b0 = (j & 1) ? bg[2] : bg[0];
                    uint32_t b1 = (j & 1) ? bg[3] : bg[1];
                    mma16816(c[i][j], a[i], b0, b1);
                }
        }
    };

    load_chunk(0, 0); CP_COMMIT();
    load_chunk(1, 1); CP_COMMIT();
#pragma unroll
    for (int cc = 0; cc < 6; cc++) {
        if (cc < 5) cp_wait<1>(); else cp_wait<0>();
        __syncthreads();
        if (cc < 4) { load_chunk(cc + 2, (cc + 2) % NSTAGE); CP_COMMIT(); }
        compute(cc % NSTAGE);
    }

    int tq = lane >> 2, tr = lane & 3;

    if (MODE == 0) {
        __half* Y = reinterpret_cast<__half*>(ba.Y[z]);
#pragma unroll
        for (int i = 0; i < 2; i++)
#pragma unroll
            for (int j = 0; j < 8; j++) {
                int colb = nw0 + j * 8 + tr * 2;
#pragma unroll
                for (int h = 0; h < 2; h++) {
                    int row = r0 + mw0 + i * 16 + tq + h * 8;
                    __half2 hv = __floats2half2_rn(
                        alpha * c[i][j][h * 2 + 0] + sbias[colb],
                        alpha * c[i][j][h * 2 + 1] + sbias[colb + 1]);
                    *reinterpret_cast<__half2*>(Y + (size_t)row * CH + o0 + colb) = hv;
                }
            }
    } else {
        float* Y = reinterpret_cast<float*>(ba.Y[z]);
        const float* S = ba.S;
        float ssign = ba.ssign[z];
        float* smemf = reinterpret_cast<float*>(smem);
        __syncthreads();
        // ---- transposed staging: smemf[col * SRS + row] (conflict-free writes) ----
#pragma unroll
        for (int i = 0; i < 2; i++)
#pragma unroll
            for (int j = 0; j < 8; j++) {
                int colb = nw0 + j * 8 + tr * 2;
#pragma unroll
                for (int h = 0; h < 2; h++) {
                    int row = mw0 + i * 16 + tq + h * 8;
                    smemf[colb * SRS + row]       = c[i][j][h * 2 + 0];
                    smemf[(colb + 1) * SRS + row] = c[i][j][h * 2 + 1];
                }
            }
        __syncthreads();
        // ---- vectorized scatter: 16 cols/warp, lane owns 4 consecutive rows ----
        int b = r0 >> 12, p0r = r0 & 4095;
#pragma unroll 4
        for (int cw = wid * 16; cw < wid * 16 + 16; cw++) {
            float4 v = *reinterpret_cast<float4*>(smemf + cw * SRS + lane * 4);
            size_t addr = (((size_t)(b * CH + o0 + cw)) << 12) + p0r + lane * 4;
            float4 s = *reinterpret_cast<const float4*>(S + addr);
            float bb = sbias[cw];
            float4 o;
            o.x = v.x + bb + ssign * s.x;
            o.y = v.y + bb + ssign * s.y;
            o.z = v.z + bb + ssign * s.z;
            o.w = v.w + bb + ssign * s.w;
            *reinterpret_cast<float4*>(Y + addr) = o;
        }
    }
}

// ==================== dilated 3x3 window attention — exact R13 config ====================
// 4 units/warp, 8 lanes/unit; lane owns 8 contiguous head-dims.
// Offsets cached from pass 1 (OOB -> safe own-pixel addr, weight 0);
// pass 2 branchless fp16 hfma2 accumulation; normalization fp32 at end.
struct AttnArgs {
    const __half* q[2]; const __half* k[2]; const __half* v[2]; __half* o[2];
};

__global__ __launch_bounds__(256) void attn_kernel(AttnArgs aa)
{
    int tid  = threadIdx.x;
    int wid  = tid >> 5, lane = tid & 31;
    int g    = lane & 7;                       // lane within unit group
    int u    = blockIdx.x * 32 + wid * 4 + (lane >> 3);   // 0..196607
    int sel  = u >= 98304;
    int unit = u - sel * 98304;

    int pix  = unit & 4095;
    int t    = unit >> 12;
    int head = t & 1;  t >>= 1;
    int di   = t % 3;
    int b    = t / 3;
    int dil  = di + 1;
    int y0   = pix >> 6, x0 = pix & 63;
    int chan = di * 128 + head * 64;

    size_t sbase = (size_t)b * HWPIX * CH + chan + g * 8;  // lane's 8-dim slice
    const char* kb = reinterpret_cast<const char*>(aa.k[sel] + sbase);
    const char* vb = reinterpret_cast<const char*>(aa.v[sel] + sbase);

    uint4 qr = *reinterpret_cast<const uint4*>(aa.q[sel] + sbase + (size_t)pix * CH);
    __half2 q2[4];
    q2[0] = *reinterpret_cast<__half2*>(&qr.x);
    q2[1] = *reinterpret_cast<__half2*>(&qr.y);
    q2[2] = *reinterpret_cast<__half2*>(&qr.z);
    q2[3] = *reinterpret_cast<__half2*>(&qr.w);

    // ---- pass 1: logits + cached offsets ----
    uint32_t offs[9];
    float logit[9];
    unsigned okm = 0;
#pragma unroll
    for (int n = 0; n < 9; n++) {
        int iy = n / 3 - 1, ix = n % 3 - 1;
        int yn = y0 + iy * dil, xn = x0 + ix * dil;
        bool ok = ((unsigned)yn < 64u) && ((unsigned)xn < 64u);
        int npix = ok ? (yn * 64 + xn) : pix;       // safe address for OOB
        offs[n] = (uint32_t)npix * (CH * 2);
        okm |= (unsigned)ok << n;
        uint4 kr = *reinterpret_cast<const uint4*>(kb + offs[n]);
        __half2 acc = __hmul2(q2[0], *reinterpret_cast<__half2*>(&kr.x));
        acc = __hfma2(q2[1], *reinterpret_cast<__half2*>(&kr.y), acc);
        acc = __hfma2(q2[2], *reinterpret_cast<__half2*>(&kr.z), acc);
        acc = __hfma2(q2[3], *reinterpret_cast<__half2*>(&kr.w), acc);
        float2 f = __half22float2(acc);
        float d = f.x + f.y;
        d += __shfl_xor_sync(0xffffffffu, d, 1);
        d += __shfl_xor_sync(0xffffffffu, d, 2);
        d += __shfl_xor_sync(0xffffffffu, d, 4);
        logit[n] = ok ? d * 0.125f : 0.f;   // SCALE = 64^-0.5; OOB taps -> logit 0 (zero-padded k)
    }

    // ---- softmax ----
    float m = logit[0];
#pragma unroll
    for (int n = 1; n < 9; n++) m = fmaxf(m, logit[n]);
    float den = 0.f;
    __half2 pw[9];
#pragma unroll
    for (int n = 0; n < 9; n++) {
        float p = __expf(logit[n] - m);
        den += p;                            // zero-padded taps contribute exp(0-m)
        pw[n] = __float2half2_rn(((okm >> n) & 1u) ? p : 0.f);   // weight 0 for OOB V
    }
    float inv = 1.f / den;

    // ---- pass 2: branchless fp16 V accumulation ----
    __half2 ac[4];
    ac[0] = __floats2half2_rn(0.f, 0.f);
    ac[1] = ac[0]; ac[2] = ac[0]; ac[3] = ac[0];
#pragma unroll
    for (int n = 0; n < 9; n++) {
        uint4 vr = *reinterpret_cast<const uint4*>(vb + offs[n]);
        ac[0] = __hfma2(pw[n], *reinterpret_cast<__half2*>(&vr.x), ac[0]);
        ac[1] = __hfma2(pw[n], *reinterpret_cast<__half2*>(&vr.y), ac[1]);
        ac[2] = __hfma2(pw[n], *reinterpret_cast<__half2*>(&vr.z), ac[2]);
        ac[3] = __hfma2(pw[n], *reinterpret_cast<__half2*>(&vr.w), ac[3]);
    }

    // ---- normalize (fp32) + store 8 halves ----
    int G  = pix * 2 + head;
    int F2 = (G >> 6) * 12288 + (G & 63) * 192 + di * 64;
    uint4 ov;
    uint32_t* ovp = reinterpret_cast<uint32_t*>(&ov);
#pragma unroll
    for (int i = 0; i < 4; i++) {
        float2 f = __half22float2(ac[i]);
        __half2 h = __floats2half2_rn(f.x * inv, f.y * inv);
        ovp[i] = *reinterpret_cast<uint32_t*>(&h);
    }
    *reinterpret_cast<uint4*>(aa.o[sel] + (size_t)b * HWPIX * CH + F2 + g * 8) = ov;
}

// ==================== launch ====================
extern "C" void kernel_launch(void* const* d_in, const int* in_sizes, int n_in,
                              void* d_out, int out_size)
{
    const float* vi  = (const float*)d_in[0];
    const float* ir  = (const float*)d_in[1];
    const float* gvi = (const float*)d_in[2];
    const float* bvi = (const float*)d_in[3];
    const float* gir = (const float*)d_in[4];
    const float* bir = (const float*)d_in[5];
    const float* wq1 = (const float*)d_in[6];
    const float* bq1 = (const float*)d_in[7];
    const float* wk1 = (const float*)d_in[8];
    const float* bk1 = (const float*)d_in[9];
    const float* wv1 = (const float*)d_in[10];
    const float* bv1 = (const float*)d_in[11];
    const float* wp1 = (const float*)d_in[12];
    const float* bp1 = (const float*)d_in[13];
    const float* wq2 = (const float*)d_in[14];
    const float* bq2 = (const float*)d_in[15];
    const float* wk2 = (const float*)d_in[16];
    const float* bk2 = (const float*)d_in[17];
    const float* wv2 = (const float*)d_in[18];
    const float* bv2 = (const float*)d_in[19];
    const float* wp2 = (const float*)d_in[20];
    const float* bp2 = (const float*)d_in[21];
    float* out = (float*)d_out;

    __half *p_vifh, *p_irfh, *p_s1h, *p_axh, *p_axh2, *p_wh;
    __half *p_q1, *p_k1, *p_v1, *p_q2, *p_k2, *p_v2;
    float  *p_s1n;
    cudaGetSymbolAddress((void**)&p_vifh, g_vifh);
    cudaGetSymbolAddress((void**)&p_irfh, g_irfh);
    cudaGetSymbolAddress((void**)&p_s1h,  g_s1h);
    cudaGetSymbolAddress((void**)&p_axh,  g_axh);
    cudaGetSymbolAddress((void**)&p_axh2, g_axh2);
    cudaGetSymbolAddress((void**)&p_wh,   g_wh);
    cudaGetSymbolAddress((void**)&p_s1n,  g_s1n);
    cudaGetSymbolAddress((void**)&p_q1,   g_q1);
    cudaGetSymbolAddress((void**)&p_k1,   g_k1);
    cudaGetSymbolAddress((void**)&p_v1,   g_v1);
    cudaGetSymbolAddress((void**)&p_q2,   g_q2);
    cudaGetSymbolAddress((void**)&p_k2,   g_k2);
    cudaGetSymbolAddress((void**)&p_v2,   g_v2);

    cudaFuncSetAttribute(gemm_tc_kernel<0>, cudaFuncAttributeMaxDynamicSharedMemorySize, SM_TOTAL);
    cudaFuncSetAttribute(gemm_tc_kernel<1>, cudaFuncAttributeMaxDynamicSharedMemorySize, SM_TOTAL);
    cudaFuncSetAttribute(ln_conv_kernel,    cudaFuncAttributeMaxDynamicSharedMemorySize, LN_SMEM);

    // merged: weight fp16 conversion (blocks 0..1151) + LN (blocks 1152..2175)
    WPtrs wp;
    wp.w[0] = wq1; wp.w[1] = wk1; wp.w[2] = wv1; wp.w[3] = wp1;
    wp.w[4] = wq2; wp.w[5] = wk2; wp.w[6] = wv2; wp.w[7] = wp2;
    ln_conv_kernel<<<NCONVB + ROWS / LNP, 256, LN_SMEM>>>(wp, vi, ir, gvi, bvi, gir, bir);

    // ---- all six pre-attention GEMMs in one launch (R11 proven config) ----
    BatchArgs qkv = {};
    qkv.X[0] = p_s1h;  qkv.W[0] = p_wh + 0*WELEMS; qkv.bias[0] = bq1; qkv.Y[0] = p_q1; qkv.alpha[0] =  1.f;
    qkv.X[1] = p_vifh; qkv.W[1] = p_wh + 1*WELEMS; qkv.bias[1] = bk1; qkv.Y[1] = p_k1; qkv.alpha[1] =  1.f;
    qkv.X[2] = p_vifh; qkv.W[2] = p_wh + 2*WELEMS; qkv.bias[2] = bv1; qkv.Y[2] = p_v1; qkv.alpha[2] =  1.f;
    qkv.X[3] = p_s1h;  qkv.W[3] = p_wh + 4*WELEMS; qkv.bias[3] = bq2; qkv.Y[3] = p_q2; qkv.alpha[3] = -1.f;
    qkv.X[4] = p_irfh; qkv.W[4] = p_wh + 5*WELEMS; qkv.bias[4] = bk2; qkv.Y[4] = p_k2; qkv.alpha[4] =  1.f;
    qkv.X[5] = p_irfh; qkv.W[5] = p_wh + 6*WELEMS; qkv.bias[5] = bv2; qkv.Y[5] = p_v2; qkv.alpha[5] =  1.f;
    gemm_tc_kernel<0><<<dim3(ROWS/128, CH/128, 6), 256, SM_TOTAL>>>(qkv);

    // ---- both attentions in one launch (4 units/warp) ----
    AttnArgs aa;
    aa.q[0] = p_q1; aa.k[0] = p_k1; aa.v[0] = p_v1; aa.o[0] = p_axh;
    aa.q[1] = p_q2; aa.k[1] = p_k2; aa.v[1] = p_v2; aa.o[1] = p_axh2;
    attn_kernel<<<6144, 256>>>(aa);

    // ---- both projections (+ residual, NCHW scatter) in one launch ----
    BatchArgs pj = {};
    pj.X[0] = p_axh;  pj.W[0] = p_wh + 3*WELEMS; pj.bias[0] = bp1; pj.Y[0] = out;                      pj.alpha[0] = 1.f; pj.ssign[0] =  1.f;
    pj.X[1] = p_axh2; pj.W[1] = p_wh + 7*WELEMS; pj.bias[1] = bp2; pj.Y[1] = out + (size_t)ROWS * CH;  pj.alpha[1] = 1.f; pj.ssign[1] = -1.f;
    pj.S = p_s1n;
    gemm_tc_kernel<1><<<dim3(ROWS/128, CH/128, 2), 256, SM_TOTAL>>>(pj);
}